// round 1
// baseline (speedup 1.0000x reference)
#include <cuda_runtime.h>

// Problem constants
#define B_      8
#define Hdim    128
#define Wdim    128
#define C_      192
#define L_      (Hdim*Wdim)            // 16384
#define NHEADS  6
#define HD      32                      // head dim
#define H_SP    8
#define W_SP    16
#define NTOK    128                     // N = H_SP*W_SP
#define NWIN    128                     // nW = L/N
#define POSDIM  12
#define NBIAS   465                     // (2*8-1)*(2*16-1)
#define SCALE   0.17677669529663687f    // 32^-0.5

// Scratch (device globals — no allocation allowed)
__device__ float g_qp[B_*NHEADS*NTOK*HD];     // pooled, scaled queries
__device__ float g_rpb[NHEADS*NTOK*NTOK];     // gathered relative position bias

// ---------------------------------------------------------------------------
// Kernel 1: DynamicPosBias MLP (465 rows) + gather rpb[h][i][j]
// ---------------------------------------------------------------------------
__global__ void pos_kernel(
    const float* __restrict__ rpe,   // [465,2]
    const float* __restrict__ w0,    // [2,12]
    const float* __restrict__ b0,    // [12]
    const float* __restrict__ g1, const float* __restrict__ be1,
    const float* __restrict__ w1, const float* __restrict__ lb1,   // [12,12],[12]
    const float* __restrict__ g2, const float* __restrict__ be2,
    const float* __restrict__ w2, const float* __restrict__ lb2,
    const float* __restrict__ g3, const float* __restrict__ be3,
    const float* __restrict__ w3, const float* __restrict__ lb3,   // [12,6],[6]
    const int*   __restrict__ rel_idx) // [128,128]
{
    __shared__ float pos_s[NBIAS*NHEADS];
    int t = threadIdx.x;
    if (t < NBIAS) {
        float x[POSDIM], y[POSDIM];
        float a = rpe[2*t], b = rpe[2*t+1];
        #pragma unroll
        for (int o = 0; o < POSDIM; o++)
            x[o] = a * w0[o] + b * w0[POSDIM + o] + b0[o];

        // stage 1: ln1, relu, lin1
        {
            float m = 0.f;
            #pragma unroll
            for (int i = 0; i < POSDIM; i++) m += x[i];
            m *= (1.f/POSDIM);
            float v = 0.f;
            #pragma unroll
            for (int i = 0; i < POSDIM; i++) { float d = x[i]-m; v += d*d; }
            v *= (1.f/POSDIM);
            float inv = rsqrtf(v + 1e-5f);
            #pragma unroll
            for (int i = 0; i < POSDIM; i++)
                y[i] = fmaxf((x[i]-m)*inv*g1[i] + be1[i], 0.f);
            #pragma unroll
            for (int o = 0; o < POSDIM; o++) {
                float s = lb1[o];
                #pragma unroll
                for (int i = 0; i < POSDIM; i++) s += y[i] * w1[i*POSDIM + o];
                x[o] = s;
            }
        }
        // stage 2: ln2, relu, lin2
        {
            float m = 0.f;
            #pragma unroll
            for (int i = 0; i < POSDIM; i++) m += x[i];
            m *= (1.f/POSDIM);
            float v = 0.f;
            #pragma unroll
            for (int i = 0; i < POSDIM; i++) { float d = x[i]-m; v += d*d; }
            v *= (1.f/POSDIM);
            float inv = rsqrtf(v + 1e-5f);
            #pragma unroll
            for (int i = 0; i < POSDIM; i++)
                y[i] = fmaxf((x[i]-m)*inv*g2[i] + be2[i], 0.f);
            #pragma unroll
            for (int o = 0; o < POSDIM; o++) {
                float s = lb2[o];
                #pragma unroll
                for (int i = 0; i < POSDIM; i++) s += y[i] * w2[i*POSDIM + o];
                x[o] = s;
            }
        }
        // stage 3: ln3, relu, lin3 (12 -> 6)
        {
            float m = 0.f;
            #pragma unroll
            for (int i = 0; i < POSDIM; i++) m += x[i];
            m *= (1.f/POSDIM);
            float v = 0.f;
            #pragma unroll
            for (int i = 0; i < POSDIM; i++) { float d = x[i]-m; v += d*d; }
            v *= (1.f/POSDIM);
            float inv = rsqrtf(v + 1e-5f);
            #pragma unroll
            for (int i = 0; i < POSDIM; i++)
                y[i] = fmaxf((x[i]-m)*inv*g3[i] + be3[i], 0.f);
            #pragma unroll
            for (int o = 0; o < NHEADS; o++) {
                float s = lb3[o];
                #pragma unroll
                for (int i = 0; i < POSDIM; i++) s += y[i] * w3[i*NHEADS + o];
                pos_s[t*NHEADS + o] = s;
            }
        }
    }
    __syncthreads();
    // gather rpb[h][i*128+j] = pos[rel_idx[i*128+j]][h]
    for (int idx = t; idx < NTOK*NTOK; idx += blockDim.x) {
        int r = rel_idx[idx];
        #pragma unroll
        for (int h = 0; h < NHEADS; h++)
            g_rpb[h*(NTOK*NTOK) + idx] = pos_s[r*NHEADS + h];
    }
}

// ---------------------------------------------------------------------------
// Kernel 2: pooled query. grid=(128 windows, 8 batch), block=192 threads (=C)
// avg-pool channels [0,96), max-pool [96,192) over 16x8 spatial blocks.
// ---------------------------------------------------------------------------
__global__ void pool_kernel(const float* __restrict__ q)
{
    int c = threadIdx.x;        // 0..191
    int n = blockIdx.x;         // 0..127 (token)
    int b = blockIdx.y;         // 0..7
    int i = n >> 4;             // 0..7   (H_SP)
    int j = n & 15;             // 0..15  (W_SP)
    const float* base = q + ((size_t)b * L_) * C_ + c;
    bool is_avg = (c < 96);
    float acc = is_avg ? 0.f : -3.0e38f;
    #pragma unroll 4
    for (int yy = 0; yy < 16; yy++) {
        int y = i*16 + yy;
        const float* row = base + (size_t)(y*Wdim + j*8) * C_;
        #pragma unroll
        for (int xx = 0; xx < 8; xx++) {
            float v = row[(size_t)xx * C_];
            if (is_avg) acc += v; else acc = fmaxf(acc, v);
        }
    }
    if (is_avg) acc *= (1.f/128.f);
    int h = c >> 5, d = c & 31;
    g_qp[(((b*NHEADS) + h)*NTOK + n)*HD + d] = acc * SCALE;
}

// ---------------------------------------------------------------------------
// Kernel 3: fused attention per (window-batch w, head h).
// grid = (6, 1024), block = 256 threads, ~97 KB dynamic smem, 2 blocks/SM.
// ---------------------------------------------------------------------------
#define KV_PITCH 33
#define S_PITCH  129

__global__ void __launch_bounds__(256, 2)
attn_kernel(const float* __restrict__ kg, const float* __restrict__ vg,
            const float* __restrict__ maskg, float* __restrict__ outg)
{
    extern __shared__ float sm[];
    float* q_s  = sm;                         // 128*32   = 4096
    float* kv_s = sm + NTOK*HD;               // 128*33   = 4224
    float* S    = sm + NTOK*HD + NTOK*KV_PITCH; // 128*129 = 16512

    const int t   = threadIdx.x;
    const int h   = blockIdx.x;
    const int w   = blockIdx.y;
    const int b   = w >> 7;          // kv batch
    const int win = w & 127;
    const int hb  = win >> 3;        // 0..15
    const int wb  = win & 7;         // 0..7
    const int qb  = w & 7;           // q batch = w % B (torch .repeat ordering)

    // ---- load pooled q tile [128][32] (already scaled) ----
    {
        const float* qsrc = g_qp + (((size_t)qb*NHEADS + h)*NTOK)*HD;
        #pragma unroll
        for (int rep = 0; rep < 4; rep++) {
            int idx = t + rep*256;   // float4 index, 1024 total
            *(float4*)(q_s + idx*4) = *(const float4*)(qsrc + idx*4);
        }
    }
    // ---- load k window [128][32] into padded smem ----
    {
        #pragma unroll
        for (int rep = 0; rep < 4; rep++) {
            int idx = t + rep*256;          // 1024 float4 chunks
            int row = idx >> 3;             // token 0..127
            int q4  = idx & 7;
            int y = hb*8 + (row >> 4);
            int x = wb*16 + (row & 15);
            const float* gp = kg + ((size_t)(b*L_ + y*Wdim + x))*C_ + h*HD + q4*4;
            float4 v4 = *(const float4*)gp;
            float* dst = kv_s + row*KV_PITCH + q4*4;
            dst[0] = v4.x; dst[1] = v4.y; dst[2] = v4.z; dst[3] = v4.w;
        }
    }
    __syncthreads();

    // ---- QK^T + rpb + mask -> S ----
    {
        const int jp = t & 63;         // j-pair index
        const int j0 = jp * 2;
        const int ig = t >> 6;         // 0..3
        float kr0[HD], kr1[HD];
        #pragma unroll
        for (int d = 0; d < HD; d++) {
            kr0[d] = kv_s[j0*KV_PITCH + d];
            kr1[d] = kv_s[(j0+1)*KV_PITCH + d];
        }
        const float* rpb_h  = g_rpb + (size_t)h * (NTOK*NTOK);
        const float* mask_w = maskg + (size_t)win * (NTOK*NTOK);
        #pragma unroll 2
        for (int rep = 0; rep < 32; rep++) {
            int i = ig + rep*4;
            float a0 = 0.f, a1 = 0.f;
            const float* qr = q_s + i*HD;
            #pragma unroll
            for (int d = 0; d < HD; d++) {
                float qv = qr[d];
                a0 += qv * kr0[d];
                a1 += qv * kr1[d];
            }
            float2 rb = *(const float2*)(rpb_h  + i*NTOK + j0);
            float2 mk = *(const float2*)(mask_w + i*NTOK + j0);
            S[i*S_PITCH + j0    ] = a0 + rb.x + mk.x;
            S[i*S_PITCH + j0 + 1] = a1 + rb.y + mk.y;
        }
    }
    __syncthreads();

    // ---- prefetch v (regs), softmax rows, then store v to smem ----
    float4 vbuf[4];
    {
        #pragma unroll
        for (int rep = 0; rep < 4; rep++) {
            int idx = t + rep*256;
            int row = idx >> 3;
            int q4  = idx & 7;
            int y = hb*8 + (row >> 4);
            int x = wb*16 + (row & 15);
            const float* gp = vg + ((size_t)(b*L_ + y*Wdim + x))*C_ + h*HD + q4*4;
            vbuf[rep] = *(const float4*)gp;
        }
    }
    {
        const int warp = t >> 5, lane = t & 31;
        for (int rr = 0; rr < 16; rr++) {
            int i = warp*16 + rr;
            float* srow = S + i*S_PITCH;
            float e0 = srow[lane];
            float e1 = srow[lane + 32];
            float e2 = srow[lane + 64];
            float e3 = srow[lane + 96];
            float m = fmaxf(fmaxf(e0, e1), fmaxf(e2, e3));
            #pragma unroll
            for (int off = 16; off; off >>= 1)
                m = fmaxf(m, __shfl_xor_sync(0xffffffffu, m, off));
            e0 = __expf(e0 - m); e1 = __expf(e1 - m);
            e2 = __expf(e2 - m); e3 = __expf(e3 - m);
            float s = e0 + e1 + e2 + e3;
            #pragma unroll
            for (int off = 16; off; off >>= 1)
                s += __shfl_xor_sync(0xffffffffu, s, off);
            float inv = __fdividef(1.f, s);
            srow[lane]      = e0 * inv;
            srow[lane + 32] = e1 * inv;
            srow[lane + 64] = e2 * inv;
            srow[lane + 96] = e3 * inv;
        }
    }
    {   // store prefetched v into kv_s (k no longer needed)
        #pragma unroll
        for (int rep = 0; rep < 4; rep++) {
            int idx = t + rep*256;
            int row = idx >> 3;
            int q4  = idx & 7;
            float* dst = kv_s + row*KV_PITCH + q4*4;
            dst[0] = vbuf[rep].x; dst[1] = vbuf[rep].y;
            dst[2] = vbuf[rep].z; dst[3] = vbuf[rep].w;
        }
    }
    __syncthreads();

    // ---- P @ V : each thread 4 rows x 4 dims ----
    {
        const int dg = t & 7;          // d group
        const int d0 = dg * 4;
        const int ig = t >> 3;         // 0..31
        const int ibase = ig * 4;
        float acc[4][4];
        #pragma unroll
        for (int a = 0; a < 4; a++)
            #pragma unroll
            for (int c = 0; c < 4; c++) acc[a][c] = 0.f;

        #pragma unroll 2
        for (int kk = 0; kk < NTOK; kk++) {
            float vv0 = kv_s[kk*KV_PITCH + d0];
            float vv1 = kv_s[kk*KV_PITCH + d0 + 1];
            float vv2 = kv_s[kk*KV_PITCH + d0 + 2];
            float vv3 = kv_s[kk*KV_PITCH + d0 + 3];
            #pragma unroll
            for (int a = 0; a < 4; a++) {
                float s = S[(ibase + a)*S_PITCH + kk];
                acc[a][0] += s * vv0;
                acc[a][1] += s * vv1;
                acc[a][2] += s * vv2;
                acc[a][3] += s * vv3;
            }
        }
        #pragma unroll
        for (int a = 0; a < 4; a++) {
            int i = ibase + a;
            int y = hb*8 + (i >> 4);
            int x = wb*16 + (i & 15);
            float* op = outg + ((size_t)((b*Hdim + y)*Wdim + x))*C_ + h*HD + d0;
            float4 o4 = make_float4(acc[a][0], acc[a][1], acc[a][2], acc[a][3]);
            *(float4*)op = o4;
        }
    }
}

// ---------------------------------------------------------------------------
extern "C" void kernel_launch(void* const* d_in, const int* in_sizes, int n_in,
                              void* d_out, int out_size)
{
    const float* qkv  = (const float*)d_in[0];
    const float* mask = (const float*)d_in[1];
    const float* w0   = (const float*)d_in[2];
    const float* b0   = (const float*)d_in[3];
    const float* g1   = (const float*)d_in[4];
    const float* be1  = (const float*)d_in[5];
    const float* w1   = (const float*)d_in[6];
    const float* lb1  = (const float*)d_in[7];
    const float* g2   = (const float*)d_in[8];
    const float* be2  = (const float*)d_in[9];
    const float* w2   = (const float*)d_in[10];
    const float* lb2  = (const float*)d_in[11];
    const float* g3   = (const float*)d_in[12];
    const float* be3  = (const float*)d_in[13];
    const float* w3   = (const float*)d_in[14];
    const float* lb3  = (const float*)d_in[15];
    const float* rpe  = (const float*)d_in[16];
    const int*   rel  = (const int*)d_in[17];

    const float* q_g = qkv;
    const float* k_g = qkv + (size_t)B_ * L_ * C_;
    const float* v_g = qkv + 2 * (size_t)B_ * L_ * C_;
    float* out = (float*)d_out;

    // pos MLP + rpb gather (tiny)
    pos_kernel<<<1, 512>>>(rpe, w0, b0, g1, be1, w1, lb1,
                           g2, be2, w2, lb2, g3, be3, w3, lb3, rel);

    // pooled q
    pool_kernel<<<dim3(NTOK, B_), C_>>>(q_g);

    // fused attention
    const int smem_bytes = (NTOK*HD + NTOK*KV_PITCH + NTOK*S_PITCH) * (int)sizeof(float);
    cudaFuncSetAttribute(attn_kernel, cudaFuncAttributeMaxDynamicSharedMemorySize, smem_bytes);
    attn_kernel<<<dim3(NHEADS, B_*NWIN), 256, smem_bytes>>>(k_g, v_g, mask, out);
}

// round 2
// speedup vs baseline: 1.2685x; 1.2685x over previous
#include <cuda_runtime.h>

// Problem constants
#define B_      8
#define Hdim    128
#define Wdim    128
#define C_      192
#define L_      (Hdim*Wdim)            // 16384
#define NHEADS  6
#define HD      32                      // head dim
#define H_SP    8
#define W_SP    16
#define NTOK    128                     // N = H_SP*W_SP
#define NWIN    128                     // nW = L/N
#define POSDIM  12
#define NBIAS   465                     // (2*8-1)*(2*16-1)
#define SCALE   0.17677669529663687f    // 32^-0.5

// Scratch (device globals — no allocation allowed)
__device__ float g_qp[B_*NHEADS*NTOK*HD];     // pooled, scaled queries (tf32-rounded)
__device__ float g_pos[NBIAS*NHEADS];         // pos MLP output
__device__ float g_rpb[NHEADS*NTOK*NTOK];     // gathered relative position bias

__device__ __forceinline__ float to_tf32(float x) {
    asm("cvt.rna.tf32.f32 %0, %1;" : "=f"(x) : "f"(x));
    return x;
}

__device__ __forceinline__ void mma_tf32(
    float& c0, float& c1, float& c2, float& c3,
    float a0, float a1, float a2, float a3, float b0, float b1)
{
    asm volatile(
        "mma.sync.aligned.m16n8k8.row.col.f32.tf32.tf32.f32 "
        "{%0,%1,%2,%3}, {%4,%5,%6,%7}, {%8,%9}, {%0,%1,%2,%3};"
        : "+f"(c0), "+f"(c1), "+f"(c2), "+f"(c3)
        : "r"(__float_as_uint(a0)), "r"(__float_as_uint(a1)),
          "r"(__float_as_uint(a2)), "r"(__float_as_uint(a3)),
          "r"(__float_as_uint(b0)), "r"(__float_as_uint(b1)));
}

// ---------------------------------------------------------------------------
// Kernel 1a: DynamicPosBias MLP (465 rows) -> g_pos.  grid=4, block=128.
// ---------------------------------------------------------------------------
__global__ void pos_mlp_kernel(
    const float* __restrict__ rpe,   // [465,2]
    const float* __restrict__ w0, const float* __restrict__ b0,
    const float* __restrict__ g1, const float* __restrict__ be1,
    const float* __restrict__ w1, const float* __restrict__ lb1,
    const float* __restrict__ g2, const float* __restrict__ be2,
    const float* __restrict__ w2, const float* __restrict__ lb2,
    const float* __restrict__ g3, const float* __restrict__ be3,
    const float* __restrict__ w3, const float* __restrict__ lb3)
{
    int t = blockIdx.x * blockDim.x + threadIdx.x;
    if (t >= NBIAS) return;
    float x[POSDIM], y[POSDIM];
    float a = rpe[2*t], b = rpe[2*t+1];
    #pragma unroll
    for (int o = 0; o < POSDIM; o++)
        x[o] = a * w0[o] + b * w0[POSDIM + o] + b0[o];

    #pragma unroll
    for (int stage = 0; stage < 3; stage++) {
        const float* g  = stage == 0 ? g1  : (stage == 1 ? g2  : g3);
        const float* be = stage == 0 ? be1 : (stage == 1 ? be2 : be3);
        float m = 0.f;
        #pragma unroll
        for (int i = 0; i < POSDIM; i++) m += x[i];
        m *= (1.f/POSDIM);
        float v = 0.f;
        #pragma unroll
        for (int i = 0; i < POSDIM; i++) { float d = x[i]-m; v += d*d; }
        v *= (1.f/POSDIM);
        float inv = rsqrtf(v + 1e-5f);
        #pragma unroll
        for (int i = 0; i < POSDIM; i++)
            y[i] = fmaxf((x[i]-m)*inv*g[i] + be[i], 0.f);
        if (stage < 2) {
            const float* w  = stage == 0 ? w1  : w2;
            const float* lb = stage == 0 ? lb1 : lb2;
            #pragma unroll
            for (int o = 0; o < POSDIM; o++) {
                float s = lb[o];
                #pragma unroll
                for (int i = 0; i < POSDIM; i++) s += y[i] * w[i*POSDIM + o];
                x[o] = s;
            }
        } else {
            #pragma unroll
            for (int o = 0; o < NHEADS; o++) {
                float s = lb3[o];
                #pragma unroll
                for (int i = 0; i < POSDIM; i++) s += y[i] * w3[i*NHEADS + o];
                g_pos[t*NHEADS + o] = s;
            }
        }
    }
}

// ---------------------------------------------------------------------------
// Kernel 1b: gather rpb[h][i][j] = pos[rel_idx[i][j]][h].  grid=64, block=256.
// ---------------------------------------------------------------------------
__global__ void gather_kernel(const int* __restrict__ rel_idx)
{
    int idx = blockIdx.x * 256 + threadIdx.x;   // 0..16383
    int r = rel_idx[idx];
    #pragma unroll
    for (int h = 0; h < NHEADS; h++)
        g_rpb[h*(NTOK*NTOK) + idx] = g_pos[r*NHEADS + h];
}

// ---------------------------------------------------------------------------
// Kernel 2: pooled query (avg first 96 ch, max last 96) + scale + tf32 round.
// ---------------------------------------------------------------------------
__global__ void pool_kernel(const float* __restrict__ q)
{
    int c = threadIdx.x;        // 0..191
    int n = blockIdx.x;         // token 0..127
    int b = blockIdx.y;         // batch
    int i = n >> 4;
    int j = n & 15;
    const float* base = q + ((size_t)b * L_) * C_ + c;
    bool is_avg = (c < 96);
    float acc = is_avg ? 0.f : -3.0e38f;
    #pragma unroll 4
    for (int yy = 0; yy < 16; yy++) {
        int y = i*16 + yy;
        const float* row = base + (size_t)(y*Wdim + j*8) * C_;
        #pragma unroll
        for (int xx = 0; xx < 8; xx++) {
            float v = row[(size_t)xx * C_];
            if (is_avg) acc += v; else acc = fmaxf(acc, v);
        }
    }
    if (is_avg) acc *= (1.f/128.f);
    int h = c >> 5, d = c & 31;
    g_qp[(((b*NHEADS) + h)*NTOK + n)*HD + d] = to_tf32(acc * SCALE);
}

// ---------------------------------------------------------------------------
// Kernel 3: fused attention with tf32 mma.sync, per (head, window-batch).
// grid=(6, 1024), block=256 (8 warps), ~106KB smem, 2 blocks/SM.
// ---------------------------------------------------------------------------
#define QP 36   // q smem pitch (floats)  -> conflict-free A-frag loads
#define KP 36   // k smem pitch           -> conflict-free B-frag loads
#define VP 40   // v smem pitch           -> conflict-free B-frag loads
#define SP 136  // S smem pitch           -> conflict-free everywhere

__global__ void __launch_bounds__(256, 2)
attn_kernel(const float* __restrict__ kg, const float* __restrict__ vg,
            const float* __restrict__ maskg, float* __restrict__ outg)
{
    extern __shared__ float sm[];
    float* q_s  = sm;                       // 128*36 = 4608
    float* kv_s = sm + NTOK*QP;             // 128*40 = 5120 (k uses pitch 36)
    float* S    = sm + NTOK*QP + NTOK*VP;   // 128*136 = 17408

    const int t    = threadIdx.x;
    const int warp = t >> 5;
    const int lane = t & 31;
    const int g    = lane >> 2;     // groupID
    const int tig  = lane & 3;      // thread in group
    const int h    = blockIdx.x;
    const int w    = blockIdx.y;
    const int b    = w >> 7;
    const int win  = w & 127;
    const int hb   = win >> 3;
    const int wb   = win & 7;
    const int qb   = w & 7;         // q batch (torch .repeat ordering)

    // ---- load q (tf32 already) and k (convert) into smem ----
    {
        const float* qsrc = g_qp + (((size_t)qb*NHEADS + h)*NTOK)*HD;
        #pragma unroll
        for (int rep = 0; rep < 4; rep++) {
            int idx = t + rep*256;          // float4 index
            int row = idx >> 3, q4 = idx & 7;
            float4 v4 = *(const float4*)(qsrc + idx*4);
            *(float4*)(q_s + row*QP + q4*4) = v4;
        }
        #pragma unroll
        for (int rep = 0; rep < 4; rep++) {
            int idx = t + rep*256;
            int row = idx >> 3, q4 = idx & 7;
            int y = hb*8 + (row >> 4);
            int x = wb*16 + (row & 15);
            const float* gp = kg + ((size_t)(b*L_ + y*Wdim + x))*C_ + h*HD + q4*4;
            float4 v4 = *(const float4*)gp;
            v4.x = to_tf32(v4.x); v4.y = to_tf32(v4.y);
            v4.z = to_tf32(v4.z); v4.w = to_tf32(v4.w);
            *(float4*)(kv_s + row*KP + q4*4) = v4;
        }
    }
    __syncthreads();

    // ---- QK^T via tf32 mma: warp handles rows [warp*16, warp*16+16) ----
    {
        const int i0 = warp * 16;
        float a[4][4];
        #pragma unroll
        for (int ks = 0; ks < 4; ks++) {
            const float* qp0 = q_s + ks*8 + tig;
            a[ks][0] = qp0[(i0 + g)     * QP];
            a[ks][1] = qp0[(i0 + g + 8) * QP];
            a[ks][2] = qp0[(i0 + g)     * QP + 4];
            a[ks][3] = qp0[(i0 + g + 8) * QP + 4];
        }
        const float* rpb_h  = g_rpb + (size_t)h * (NTOK*NTOK);
        const float* mask_w = maskg + (size_t)win * (NTOK*NTOK);
        #pragma unroll 4
        for (int nt = 0; nt < 16; nt++) {
            float c0 = 0.f, c1 = 0.f, c2 = 0.f, c3 = 0.f;
            #pragma unroll
            for (int ks = 0; ks < 4; ks++) {
                const float* kp0 = kv_s + (nt*8 + g)*KP + ks*8 + tig;
                float b0 = kp0[0];
                float b1 = kp0[4];
                mma_tf32(c0, c1, c2, c3, a[ks][0], a[ks][1], a[ks][2], a[ks][3], b0, b1);
            }
            int i = i0 + g;
            int j = nt*8 + 2*tig;
            float2 rb = *(const float2*)(rpb_h  + i*NTOK + j);
            float2 mk = *(const float2*)(mask_w + i*NTOK + j);
            *(float2*)(S + i*SP + j) = make_float2(c0 + rb.x + mk.x, c1 + rb.y + mk.y);
            i += 8;
            rb = *(const float2*)(rpb_h  + i*NTOK + j);
            mk = *(const float2*)(mask_w + i*NTOK + j);
            *(float2*)(S + i*SP + j) = make_float2(c2 + rb.x + mk.x, c3 + rb.y + mk.y);
        }
    }
    __syncthreads();

    // ---- prefetch v to regs, softmax, then store v (tf32) to smem ----
    float4 vbuf[4];
    {
        #pragma unroll
        for (int rep = 0; rep < 4; rep++) {
            int idx = t + rep*256;
            int row = idx >> 3, q4 = idx & 7;
            int y = hb*8 + (row >> 4);
            int x = wb*16 + (row & 15);
            const float* gp = vg + ((size_t)(b*L_ + y*Wdim + x))*C_ + h*HD + q4*4;
            vbuf[rep] = *(const float4*)gp;
        }
    }
    {
        for (int rr = 0; rr < 16; rr++) {
            int i = warp*16 + rr;
            float* srow = S + i*SP;
            float e0 = srow[lane];
            float e1 = srow[lane + 32];
            float e2 = srow[lane + 64];
            float e3 = srow[lane + 96];
            float m = fmaxf(fmaxf(e0, e1), fmaxf(e2, e3));
            #pragma unroll
            for (int off = 16; off; off >>= 1)
                m = fmaxf(m, __shfl_xor_sync(0xffffffffu, m, off));
            e0 = __expf(e0 - m); e1 = __expf(e1 - m);
            e2 = __expf(e2 - m); e3 = __expf(e3 - m);
            float s = e0 + e1 + e2 + e3;
            #pragma unroll
            for (int off = 16; off; off >>= 1)
                s += __shfl_xor_sync(0xffffffffu, s, off);
            float inv = __fdividef(1.f, s);
            srow[lane]      = e0 * inv;
            srow[lane + 32] = e1 * inv;
            srow[lane + 64] = e2 * inv;
            srow[lane + 96] = e3 * inv;
        }
    }
    __syncthreads();   // ensure all QK reads of kv_s done before overwrite (softmax barrier covers)
    {
        #pragma unroll
        for (int rep = 0; rep < 4; rep++) {
            int idx = t + rep*256;
            int row = idx >> 3, q4 = idx & 7;
            float4 v4 = vbuf[rep];
            v4.x = to_tf32(v4.x); v4.y = to_tf32(v4.y);
            v4.z = to_tf32(v4.z); v4.w = to_tf32(v4.w);
            *(float4*)(kv_s + row*VP + q4*4) = v4;
        }
    }
    __syncthreads();

    // ---- P @ V via tf32 mma: warp rows [warp*16..), cols 0..31 (4 n-tiles) ----
    {
        const int i0 = warp * 16;
        float c[4][4];
        #pragma unroll
        for (int nt = 0; nt < 4; nt++)
            #pragma unroll
            for (int k = 0; k < 4; k++) c[nt][k] = 0.f;

        #pragma unroll 4
        for (int ks = 0; ks < 16; ks++) {
            const float* sp0 = S + ks*8 + tig;
            float a0 = sp0[(i0 + g)     * SP];
            float a1 = sp0[(i0 + g + 8) * SP];
            float a2 = sp0[(i0 + g)     * SP + 4];
            float a3 = sp0[(i0 + g + 8) * SP + 4];
            #pragma unroll
            for (int nt = 0; nt < 4; nt++) {
                float b0 = kv_s[(ks*8 + tig)    *VP + nt*8 + g];
                float b1 = kv_s[(ks*8 + tig + 4)*VP + nt*8 + g];
                mma_tf32(c[nt][0], c[nt][1], c[nt][2], c[nt][3], a0, a1, a2, a3, b0, b1);
            }
        }
        // store: rows i0+g and i0+g+8, cols nt*8 + 2*tig (+1)
        #pragma unroll
        for (int nt = 0; nt < 4; nt++) {
            int d = nt*8 + 2*tig;
            int i = i0 + g;
            int y = hb*8 + (i >> 4);
            int x = wb*16 + (i & 15);
            float* op = outg + ((size_t)((b*Hdim + y)*Wdim + x))*C_ + h*HD + d;
            *(float2*)op = make_float2(c[nt][0], c[nt][1]);
            i += 8;
            y = hb*8 + (i >> 4);
            x = wb*16 + (i & 15);
            op = outg + ((size_t)((b*Hdim + y)*Wdim + x))*C_ + h*HD + d;
            *(float2*)op = make_float2(c[nt][2], c[nt][3]);
        }
    }
}

// ---------------------------------------------------------------------------
extern "C" void kernel_launch(void* const* d_in, const int* in_sizes, int n_in,
                              void* d_out, int out_size)
{
    const float* qkv  = (const float*)d_in[0];
    const float* mask = (const float*)d_in[1];
    const float* w0   = (const float*)d_in[2];
    const float* b0   = (const float*)d_in[3];
    const float* g1   = (const float*)d_in[4];
    const float* be1  = (const float*)d_in[5];
    const float* w1   = (const float*)d_in[6];
    const float* lb1  = (const float*)d_in[7];
    const float* g2   = (const float*)d_in[8];
    const float* be2  = (const float*)d_in[9];
    const float* w2   = (const float*)d_in[10];
    const float* lb2  = (const float*)d_in[11];
    const float* g3   = (const float*)d_in[12];
    const float* be3  = (const float*)d_in[13];
    const float* w3   = (const float*)d_in[14];
    const float* lb3  = (const float*)d_in[15];
    const float* rpe  = (const float*)d_in[16];
    const int*   rel  = (const int*)d_in[17];

    const float* q_g = qkv;
    const float* k_g = qkv + (size_t)B_ * L_ * C_;
    const float* v_g = qkv + 2 * (size_t)B_ * L_ * C_;
    float* out = (float*)d_out;

    pos_mlp_kernel<<<4, 128>>>(rpe, w0, b0, g1, be1, w1, lb1,
                               g2, be2, w2, lb2, g3, be3, w3, lb3);
    gather_kernel<<<64, 256>>>(rel);
    pool_kernel<<<dim3(NTOK, B_), C_>>>(q_g);

    const int smem_bytes = (NTOK*QP + NTOK*VP + NTOK*SP) * (int)sizeof(float);
    cudaFuncSetAttribute(attn_kernel, cudaFuncAttributeMaxDynamicSharedMemorySize, smem_bytes);
    attn_kernel<<<dim3(NHEADS, B_*NWIN), 256, smem_bytes>>>(k_g, v_g, mask, out);
}

// round 3
// speedup vs baseline: 1.3260x; 1.0454x over previous
#include <cuda_runtime.h>

// Problem constants
#define B_      8
#define Hdim    128
#define Wdim    128
#define C_      192
#define L_      (Hdim*Wdim)            // 16384
#define NHEADS  6
#define HD      32
#define H_SP    8
#define W_SP    16
#define NTOK    128
#define NWIN    128
#define POSDIM  12
#define NBIAS   465
#define SCALE   0.17677669529663687f    // 32^-0.5
#define LOG2E   1.4426950408889634f

// Scratch (device globals — no allocation allowed)
__device__ float g_qp[B_*NHEADS*NTOK*HD];           // pooled queries, scaled by SCALE*LOG2E, tf32
__device__ float g_pos[NBIAS*NHEADS];               // pos MLP output
__device__ float g_bias[NWIN*NHEADS*NTOK*NTOK];     // (rpb+mask)*LOG2E, 50MB

__device__ __forceinline__ float to_tf32(float x) {
    asm("cvt.rna.tf32.f32 %0, %1;" : "=f"(x) : "f"(x));
    return x;
}
__device__ __forceinline__ float ex2(float x) {
    asm("ex2.approx.ftz.f32 %0, %1;" : "=f"(x) : "f"(x));
    return x;
}

__device__ __forceinline__ void mma_tf32(
    float& c0, float& c1, float& c2, float& c3,
    float a0, float a1, float a2, float a3, float b0, float b1)
{
    asm volatile(
        "mma.sync.aligned.m16n8k8.row.col.f32.tf32.tf32.f32 "
        "{%0,%1,%2,%3}, {%4,%5,%6,%7}, {%8,%9}, {%0,%1,%2,%3};"
        : "+f"(c0), "+f"(c1), "+f"(c2), "+f"(c3)
        : "r"(__float_as_uint(a0)), "r"(__float_as_uint(a1)),
          "r"(__float_as_uint(a2)), "r"(__float_as_uint(a3)),
          "r"(__float_as_uint(b0)), "r"(__float_as_uint(b1)));
}

// ---------------------------------------------------------------------------
// Kernel 1: DynamicPosBias MLP (465 rows) -> g_pos.
// ---------------------------------------------------------------------------
__global__ void pos_mlp_kernel(
    const float* __restrict__ rpe,
    const float* __restrict__ w0, const float* __restrict__ b0,
    const float* __restrict__ g1, const float* __restrict__ be1,
    const float* __restrict__ w1, const float* __restrict__ lb1,
    const float* __restrict__ g2, const float* __restrict__ be2,
    const float* __restrict__ w2, const float* __restrict__ lb2,
    const float* __restrict__ g3, const float* __restrict__ be3,
    const float* __restrict__ w3, const float* __restrict__ lb3)
{
    int t = blockIdx.x * blockDim.x + threadIdx.x;
    if (t >= NBIAS) return;
    float x[POSDIM], y[POSDIM];
    float a = rpe[2*t], b = rpe[2*t+1];
    #pragma unroll
    for (int o = 0; o < POSDIM; o++)
        x[o] = a * w0[o] + b * w0[POSDIM + o] + b0[o];

    #pragma unroll
    for (int stage = 0; stage < 3; stage++) {
        const float* g  = stage == 0 ? g1  : (stage == 1 ? g2  : g3);
        const float* be = stage == 0 ? be1 : (stage == 1 ? be2 : be3);
        float m = 0.f;
        #pragma unroll
        for (int i = 0; i < POSDIM; i++) m += x[i];
        m *= (1.f/POSDIM);
        float v = 0.f;
        #pragma unroll
        for (int i = 0; i < POSDIM; i++) { float d = x[i]-m; v += d*d; }
        v *= (1.f/POSDIM);
        float inv = rsqrtf(v + 1e-5f);
        #pragma unroll
        for (int i = 0; i < POSDIM; i++)
            y[i] = fmaxf((x[i]-m)*inv*g[i] + be[i], 0.f);
        if (stage < 2) {
            const float* w  = stage == 0 ? w1  : w2;
            const float* lb = stage == 0 ? lb1 : lb2;
            #pragma unroll
            for (int o = 0; o < POSDIM; o++) {
                float s = lb[o];
                #pragma unroll
                for (int i = 0; i < POSDIM; i++) s += y[i] * w[i*POSDIM + o];
                x[o] = s;
            }
        } else {
            #pragma unroll
            for (int o = 0; o < NHEADS; o++) {
                float s = lb3[o];
                #pragma unroll
                for (int i = 0; i < POSDIM; i++) s += y[i] * w3[i*NHEADS + o];
                g_pos[t*NHEADS + o] = s;
            }
        }
    }
}

// ---------------------------------------------------------------------------
// Kernel 2: combined bias = (pos[rel_idx] + mask) * LOG2E.
// grid (64, NHEADS, NWIN), block 256.
// ---------------------------------------------------------------------------
__global__ void bias_kernel(const float* __restrict__ mask,
                            const int* __restrict__ rel_idx)
{
    int idx = blockIdx.x * 256 + threadIdx.x;   // 0..16383
    int h   = blockIdx.y;
    int win = blockIdx.z;
    float p = g_pos[rel_idx[idx]*NHEADS + h];
    float m = mask[(size_t)win*(NTOK*NTOK) + idx];
    g_bias[(((size_t)win*NHEADS + h)<<14) + idx] = (p + m) * LOG2E;
}

// ---------------------------------------------------------------------------
// Kernel 3: pooled query + scale*log2e + tf32 round.
// ---------------------------------------------------------------------------
__global__ void pool_kernel(const float* __restrict__ q)
{
    int c = threadIdx.x;        // 0..191
    int n = blockIdx.x;         // token
    int b = blockIdx.y;         // batch
    int i = n >> 4;
    int j = n & 15;
    const float* base = q + ((size_t)b * L_) * C_ + c;
    bool is_avg = (c < 96);
    float acc = is_avg ? 0.f : -3.0e38f;
    #pragma unroll 4
    for (int yy = 0; yy < 16; yy++) {
        int y = i*16 + yy;
        const float* row = base + (size_t)(y*Wdim + j*8) * C_;
        #pragma unroll
        for (int xx = 0; xx < 8; xx++) {
            float v = row[(size_t)xx * C_];
            if (is_avg) acc += v; else acc = fmaxf(acc, v);
        }
    }
    if (is_avg) acc *= (1.f/128.f);
    int h = c >> 5, d = c & 31;
    g_qp[(((b*NHEADS) + h)*NTOK + n)*HD + d] = to_tf32(acc * (SCALE * LOG2E));
}

// ---------------------------------------------------------------------------
// Kernel 4: fused attention, tf32 mma. grid=(6,1024), block=256, 2 blocks/SM.
// ---------------------------------------------------------------------------
#define QP 36
#define KP 36
#define VP 40
#define SP 132

__global__ void __launch_bounds__(256, 2)
attn_kernel(const float* __restrict__ kg, const float* __restrict__ vg,
            float* __restrict__ outg)
{
    extern __shared__ float sm[];
    float* q_s  = sm;                       // 128*36
    float* kv_s = sm + NTOK*QP;             // 128*40 (k at pitch 36, v at 40)
    float* S    = sm + NTOK*QP + NTOK*VP;   // 128*132

    const int t    = threadIdx.x;
    const int warp = t >> 5;
    const int lane = t & 31;
    const int g    = lane >> 2;
    const int tig  = lane & 3;
    const int h    = blockIdx.x;
    const int w    = blockIdx.y;
    const int b    = w >> 7;
    const int win  = w & 127;
    const int hb   = win >> 3;
    const int wb   = win & 7;
    const int qb   = w & 7;

    // ---- load q + k into smem; prefetch v into regs ----
    float4 vbuf[4];
    {
        const float* qsrc = g_qp + (((size_t)qb*NHEADS + h)*NTOK)*HD;
        #pragma unroll
        for (int rep = 0; rep < 4; rep++) {
            int idx = t + rep*256;
            int row = idx >> 3, q4 = idx & 7;
            float4 v4 = *(const float4*)(qsrc + idx*4);
            *(float4*)(q_s + row*QP + q4*4) = v4;
        }
        #pragma unroll
        for (int rep = 0; rep < 4; rep++) {
            int idx = t + rep*256;
            int row = idx >> 3, q4 = idx & 7;
            int y = hb*8 + (row >> 4);
            int x = wb*16 + (row & 15);
            size_t off = ((size_t)(b*L_ + y*Wdim + x))*C_ + h*HD + q4*4;
            float4 v4 = *(const float4*)(kg + off);
            v4.x = to_tf32(v4.x); v4.y = to_tf32(v4.y);
            v4.z = to_tf32(v4.z); v4.w = to_tf32(v4.w);
            *(float4*)(kv_s + row*KP + q4*4) = v4;
            vbuf[rep] = *(const float4*)(vg + off);   // prefetch v
        }
    }
    __syncthreads();

    // ---- store v to smem (k no longer needed after QK; but QK reads k below!)
    // NOTE: v store must wait until QK B-frag reads complete — so it happens
    // after the QK phase barrier. QK first:

    // ---- QK^T via tf32 mma: warp tile 32 rows x 64 cols ----
    {
        const int wm = warp >> 1;
        const int wn = warp & 1;
        const int i0 = wm * 32;
        const int jb = wn * 64;
        float a[2][4][4];
        #pragma unroll
        for (int mt = 0; mt < 2; mt++) {
            int ib = i0 + mt*16;
            #pragma unroll
            for (int ks = 0; ks < 4; ks++) {
                const float* qp0 = q_s + ks*8 + tig;
                a[mt][ks][0] = qp0[(ib + g)     * QP];
                a[mt][ks][1] = qp0[(ib + g + 8) * QP];
                a[mt][ks][2] = qp0[(ib + g)     * QP + 4];
                a[mt][ks][3] = qp0[(ib + g + 8) * QP + 4];
            }
        }
        const float* bias_p = g_bias + (((size_t)win*NHEADS + h) << 14);
        #pragma unroll 2
        for (int nt = 0; nt < 8; nt++) {
            int j0 = jb + nt*8;
            float b0[4], b1[4];
            #pragma unroll
            for (int ks = 0; ks < 4; ks++) {
                const float* kp0 = kv_s + (j0 + g)*KP + ks*8 + tig;
                b0[ks] = kp0[0];
                b1[ks] = kp0[4];
            }
            #pragma unroll
            for (int mt = 0; mt < 2; mt++) {
                float c0 = 0.f, c1 = 0.f, c2 = 0.f, c3 = 0.f;
                #pragma unroll
                for (int ks = 0; ks < 4; ks++)
                    mma_tf32(c0, c1, c2, c3,
                             a[mt][ks][0], a[mt][ks][1], a[mt][ks][2], a[mt][ks][3],
                             b0[ks], b1[ks]);
                int i = i0 + mt*16 + g;
                int j = j0 + 2*tig;
                float2 bi = *(const float2*)(bias_p + i*NTOK + j);
                *(float2*)(S + i*SP + j) = make_float2(c0 + bi.x, c1 + bi.y);
                i += 8;
                bi = *(const float2*)(bias_p + i*NTOK + j);
                *(float2*)(S + i*SP + j) = make_float2(c2 + bi.x, c3 + bi.y);
            }
        }
    }
    __syncthreads();

    // ---- store prefetched v (tf32) into kv_s ----
    {
        #pragma unroll
        for (int rep = 0; rep < 4; rep++) {
            int idx = t + rep*256;
            int row = idx >> 3, q4 = idx & 7;
            float4 v4 = vbuf[rep];
            v4.x = to_tf32(v4.x); v4.y = to_tf32(v4.y);
            v4.z = to_tf32(v4.z); v4.w = to_tf32(v4.w);
            *(float4*)(kv_s + row*VP + q4*4) = v4;
        }
    }

    // ---- softmax rows (base-2), P stored tf32-rounded ----
    {
        for (int rr = 0; rr < 16; rr++) {
            int i = warp*16 + rr;
            float* srow = S + i*SP;
            float e0 = srow[lane];
            float e1 = srow[lane + 32];
            float e2 = srow[lane + 64];
            float e3 = srow[lane + 96];
            float m = fmaxf(fmaxf(e0, e1), fmaxf(e2, e3));
            #pragma unroll
            for (int off = 16; off; off >>= 1)
                m = fmaxf(m, __shfl_xor_sync(0xffffffffu, m, off));
            e0 = ex2(e0 - m); e1 = ex2(e1 - m);
            e2 = ex2(e2 - m); e3 = ex2(e3 - m);
            float s = e0 + e1 + e2 + e3;
            #pragma unroll
            for (int off = 16; off; off >>= 1)
                s += __shfl_xor_sync(0xffffffffu, s, off);
            float inv = __fdividef(1.f, s);
            srow[lane]      = to_tf32(e0 * inv);
            srow[lane + 32] = to_tf32(e1 * inv);
            srow[lane + 64] = to_tf32(e2 * inv);
            srow[lane + 96] = to_tf32(e3 * inv);
        }
    }
    __syncthreads();

    // ---- P @ V via tf32 mma: warp rows [warp*16..+16), cols 0..31 ----
    {
        const int i0 = warp * 16;
        float c[4][4];
        #pragma unroll
        for (int nt = 0; nt < 4; nt++)
            #pragma unroll
            for (int k = 0; k < 4; k++) c[nt][k] = 0.f;

        #pragma unroll 4
        for (int ks = 0; ks < 16; ks++) {
            const float* sp0 = S + ks*8 + tig;
            float a0 = sp0[(i0 + g)     * SP];
            float a1 = sp0[(i0 + g + 8) * SP];
            float a2 = sp0[(i0 + g)     * SP + 4];
            float a3 = sp0[(i0 + g + 8) * SP + 4];
            #pragma unroll
            for (int nt = 0; nt < 4; nt++) {
                float b0 = kv_s[(ks*8 + tig)    *VP + nt*8 + g];
                float b1 = kv_s[(ks*8 + tig + 4)*VP + nt*8 + g];
                mma_tf32(c[nt][0], c[nt][1], c[nt][2], c[nt][3], a0, a1, a2, a3, b0, b1);
            }
        }
        #pragma unroll
        for (int nt = 0; nt < 4; nt++) {
            int d = nt*8 + 2*tig;
            int i = i0 + g;
            int y = hb*8 + (i >> 4);
            int x = wb*16 + (i & 15);
            float* op = outg + ((size_t)((b*Hdim + y)*Wdim + x))*C_ + h*HD + d;
            *(float2*)op = make_float2(c[nt][0], c[nt][1]);
            i += 8;
            y = hb*8 + (i >> 4);
            x = wb*16 + (i & 15);
            op = outg + ((size_t)((b*Hdim + y)*Wdim + x))*C_ + h*HD + d;
            *(float2*)op = make_float2(c[nt][2], c[nt][3]);
        }
    }
}

// ---------------------------------------------------------------------------
extern "C" void kernel_launch(void* const* d_in, const int* in_sizes, int n_in,
                              void* d_out, int out_size)
{
    const float* qkv  = (const float*)d_in[0];
    const float* mask = (const float*)d_in[1];
    const float* w0   = (const float*)d_in[2];
    const float* b0   = (const float*)d_in[3];
    const float* g1   = (const float*)d_in[4];
    const float* be1  = (const float*)d_in[5];
    const float* w1   = (const float*)d_in[6];
    const float* lb1  = (const float*)d_in[7];
    const float* g2   = (const float*)d_in[8];
    const float* be2  = (const float*)d_in[9];
    const float* w2   = (const float*)d_in[10];
    const float* lb2  = (const float*)d_in[11];
    const float* g3   = (const float*)d_in[12];
    const float* be3  = (const float*)d_in[13];
    const float* w3   = (const float*)d_in[14];
    const float* lb3  = (const float*)d_in[15];
    const float* rpe  = (const float*)d_in[16];
    const int*   rel  = (const int*)d_in[17];

    const float* q_g = qkv;
    const float* k_g = qkv + (size_t)B_ * L_ * C_;
    const float* v_g = qkv + 2 * (size_t)B_ * L_ * C_;
    float* out = (float*)d_out;

    pos_mlp_kernel<<<4, 128>>>(rpe, w0, b0, g1, be1, w1, lb1,
                               g2, be2, w2, lb2, g3, be3, w3, lb3);
    bias_kernel<<<dim3(64, NHEADS, NWIN), 256>>>(mask, rel);
    pool_kernel<<<dim3(NTOK, B_), C_>>>(q_g);

    const int smem_bytes = (NTOK*QP + NTOK*VP + NTOK*SP) * (int)sizeof(float);
    cudaFuncSetAttribute(attn_kernel, cudaFuncAttributeMaxDynamicSharedMemorySize, smem_bytes);
    attn_kernel<<<dim3(NHEADS, B_*NWIN), 256, smem_bytes>>>(k_g, v_g, out);
}

// round 5
// speedup vs baseline: 1.6038x; 1.2095x over previous
#include <cuda_runtime.h>
#include <cuda_fp16.h>
#include <cstdint>

#define B_      8
#define Hdim    128
#define Wdim    128
#define C_      192
#define L_      (Hdim*Wdim)
#define NHEADS  6
#define HD      32
#define NTOK    128
#define NWIN    128
#define POSDIM  12
#define NBIAS   465
#define SCALE   0.17677669529663687f
#define LOG2E   1.4426950408889634f

// Scratch (device globals)
__device__ __half g_qph[B_*NHEADS*NTOK*HD];            // pooled queries, *SCALE*LOG2E, half
__device__ float  g_pos[NBIAS*NHEADS];
__device__ __half g_biash[(size_t)NWIN*NHEADS*NTOK*NTOK]; // (rpb+mask)*LOG2E, half, 25MB

__device__ __forceinline__ float ex2f(float x) {
    asm("ex2.approx.ftz.f32 %0, %1;" : "=f"(x) : "f"(x));
    return x;
}
__device__ __forceinline__ uint32_t smem_u32(const void* p) {
    uint32_t a;
    asm("{ .reg .u64 t; cvta.to.shared.u64 t, %1; cvt.u32.u64 %0, t; }" : "=r"(a) : "l"(p));
    return a;
}
__device__ __forceinline__ void ldm_x4(uint32_t& r0, uint32_t& r1, uint32_t& r2, uint32_t& r3, uint32_t addr) {
    asm volatile("ldmatrix.sync.aligned.m8n8.x4.shared.b16 {%0,%1,%2,%3}, [%4];"
                 : "=r"(r0), "=r"(r1), "=r"(r2), "=r"(r3) : "r"(addr));
}
__device__ __forceinline__ void ldm_x4_t(uint32_t& r0, uint32_t& r1, uint32_t& r2, uint32_t& r3, uint32_t addr) {
    asm volatile("ldmatrix.sync.aligned.m8n8.x4.trans.shared.b16 {%0,%1,%2,%3}, [%4];"
                 : "=r"(r0), "=r"(r1), "=r"(r2), "=r"(r3) : "r"(addr));
}
__device__ __forceinline__ void mma_f16(float* c, const uint32_t* a, uint32_t b0, uint32_t b1) {
    asm volatile(
        "mma.sync.aligned.m16n8k16.row.col.f32.f16.f16.f32 "
        "{%0,%1,%2,%3}, {%4,%5,%6,%7}, {%8,%9}, {%0,%1,%2,%3};"
        : "+f"(c[0]), "+f"(c[1]), "+f"(c[2]), "+f"(c[3])
        : "r"(a[0]), "r"(a[1]), "r"(a[2]), "r"(a[3]), "r"(b0), "r"(b1));
}
__device__ __forceinline__ uint32_t h2u(__half2 h) {
    return *reinterpret_cast<uint32_t*>(&h);
}

// 64B-row swizzle (Q,K,V tiles: 128 rows x 32 half): chunk c in [0,4)
__device__ __forceinline__ uint32_t swz64(int row, int c) {
    return row*64 + ((c ^ ((row >> 1) & 3)) << 4);
}
// 256B-row swizzle (P tile: 128 rows x 128 half): chunk c in [0,16)
__device__ __forceinline__ uint32_t swz256(int row, int c) {
    return row*256 + (((c & 8) | ((c & 7) ^ (row & 7))) << 4);
}

// smem byte offsets (attn kernel)
#define SM_Q    0            // 8KB  (overlaid by P later)
#define SM_K    8192         // 8KB  (overlaid by P later)
#define SM_P    0            // 32KB (half, 128 x 128, rows 256B, swz256)
#define SM_V    32768        // 8KB  (half, 128 x 32, rows 64B, swz64)
#define SM_S    40960        // float, 128 x 136
#define SP      136
#define SM_TOT  110592

// ---------------------------------------------------------------------------
// Kernel 1: DynamicPosBias MLP
// ---------------------------------------------------------------------------
__global__ void pos_mlp_kernel(
    const float* __restrict__ rpe,
    const float* __restrict__ w0, const float* __restrict__ b0,
    const float* __restrict__ g1, const float* __restrict__ be1,
    const float* __restrict__ w1, const float* __restrict__ lb1,
    const float* __restrict__ g2, const float* __restrict__ be2,
    const float* __restrict__ w2, const float* __restrict__ lb2,
    const float* __restrict__ g3, const float* __restrict__ be3,
    const float* __restrict__ w3, const float* __restrict__ lb3)
{
    int t = blockIdx.x * blockDim.x + threadIdx.x;
    if (t >= NBIAS) return;
    float x[POSDIM], y[POSDIM];
    float a = rpe[2*t], b = rpe[2*t+1];
    #pragma unroll
    for (int o = 0; o < POSDIM; o++)
        x[o] = a * w0[o] + b * w0[POSDIM + o] + b0[o];

    #pragma unroll
    for (int stage = 0; stage < 3; stage++) {
        const float* g  = stage == 0 ? g1  : (stage == 1 ? g2  : g3);
        const float* be = stage == 0 ? be1 : (stage == 1 ? be2 : be3);
        float m = 0.f;
        #pragma unroll
        for (int i = 0; i < POSDIM; i++) m += x[i];
        m *= (1.f/POSDIM);
        float v = 0.f;
        #pragma unroll
        for (int i = 0; i < POSDIM; i++) { float d = x[i]-m; v += d*d; }
        v *= (1.f/POSDIM);
        float inv = rsqrtf(v + 1e-5f);
        #pragma unroll
        for (int i = 0; i < POSDIM; i++)
            y[i] = fmaxf((x[i]-m)*inv*g[i] + be[i], 0.f);
        if (stage < 2) {
            const float* w  = stage == 0 ? w1  : w2;
            const float* lb = stage == 0 ? lb1 : lb2;
            #pragma unroll
            for (int o = 0; o < POSDIM; o++) {
                float s = lb[o];
                #pragma unroll
                for (int i = 0; i < POSDIM; i++) s += y[i] * w[i*POSDIM + o];
                x[o] = s;
            }
        } else {
            #pragma unroll
            for (int o = 0; o < NHEADS; o++) {
                float s = lb3[o];
                #pragma unroll
                for (int i = 0; i < POSDIM; i++) s += y[i] * w3[i*NHEADS + o];
                g_pos[t*NHEADS + o] = s;
            }
        }
    }
}

// ---------------------------------------------------------------------------
// Kernel 2: combined bias (half) = (pos[rel_idx] + mask) * LOG2E
// grid (16, 6, 128), block 256 — each thread 4 consecutive elements
// ---------------------------------------------------------------------------
__global__ void bias_kernel(const float* __restrict__ mask,
                            const int* __restrict__ rel_idx)
{
    int q = blockIdx.x * 256 + threadIdx.x;     // 4-elem group, 0..4095
    int h   = blockIdx.y;
    int win = blockIdx.z;
    int4  r = ((const int4*)rel_idx)[q];
    float4 m = ((const float4*)(mask + ((size_t)win<<14)))[q];
    __half2 lo = __floats2half2_rn((g_pos[r.x*NHEADS + h] + m.x) * LOG2E,
                                   (g_pos[r.y*NHEADS + h] + m.y) * LOG2E);
    __half2 hi = __floats2half2_rn((g_pos[r.z*NHEADS + h] + m.z) * LOG2E,
                                   (g_pos[r.w*NHEADS + h] + m.w) * LOG2E);
    uint2 out = make_uint2(h2u(lo), h2u(hi));
    ((uint2*)(g_biash + (((size_t)win*NHEADS + h)<<14)))[q] = out;
}

// ---------------------------------------------------------------------------
// Kernel 3: pooled query -> half, scaled by SCALE*LOG2E
// ---------------------------------------------------------------------------
__global__ void pool_kernel(const float* __restrict__ q)
{
    int c = threadIdx.x;
    int n = blockIdx.x;
    int b = blockIdx.y;
    int i = n >> 4;
    int j = n & 15;
    const float* base = q + ((size_t)b * L_) * C_ + c;
    bool is_avg = (c < 96);
    float acc = is_avg ? 0.f : -3.0e38f;
    #pragma unroll 4
    for (int yy = 0; yy < 16; yy++) {
        int y = i*16 + yy;
        const float* row = base + (size_t)(y*Wdim + j*8) * C_;
        #pragma unroll
        for (int xx = 0; xx < 8; xx++) {
            float v = row[(size_t)xx * C_];
            if (is_avg) acc += v; else acc = fmaxf(acc, v);
        }
    }
    if (is_avg) acc *= (1.f/128.f);
    int h = c >> 5, d = c & 31;
    g_qph[(((b*NHEADS) + h)*NTOK + n)*HD + d] = __float2half_rn(acc * (SCALE * LOG2E));
}

// ---------------------------------------------------------------------------
// Kernel 4: fused attention, fp16 m16n8k16 mma + ldmatrix.
// grid=(6,1024), block=256 (8 warps), 108KB smem, 2 blocks/SM.
// ---------------------------------------------------------------------------
__global__ void __launch_bounds__(256, 2)
attn_kernel(const float* __restrict__ kg, const float* __restrict__ vg,
            float* __restrict__ outg)
{
    extern __shared__ char smem[];
    const uint32_t sbase = smem_u32(smem);
    float* S = (float*)(smem + SM_S);

    const int t    = threadIdx.x;
    const int warp = t >> 5;
    const int lane = t & 31;
    const int g    = lane >> 2;
    const int tig  = lane & 3;
    const int h    = blockIdx.x;
    const int w    = blockIdx.y;
    const int b    = w >> 7;
    const int win  = w & 127;
    const int hb   = win >> 3;
    const int wb   = win & 7;
    const int qb   = w & 7;

    // ---- load Q (half, direct) + K/V (fp32 -> half) into swizzled smem ----
    {
        const __half* qsrc = g_qph + (((size_t)qb*NHEADS + h)*NTOK)*HD;
        #pragma unroll
        for (int rep = 0; rep < 4; rep++) {
            int idx = t + rep*256;              // 8B chunk id (1024 total)
            int row = idx >> 3, q4 = idx & 7;
            uint32_t off = swz64(row, q4 >> 1) + ((q4 & 1) << 3);
            *(uint2*)(smem + SM_Q + off) = *(const uint2*)(qsrc + idx*4);
        }
        #pragma unroll
        for (int rep = 0; rep < 4; rep++) {
            int idx = t + rep*256;
            int row = idx >> 3, q4 = idx & 7;
            int y = hb*8 + (row >> 4);
            int x = wb*16 + (row & 15);
            size_t goff = ((size_t)(b*L_ + y*Wdim + x))*C_ + h*HD + q4*4;
            uint32_t off = swz64(row, q4 >> 1) + ((q4 & 1) << 3);
            float4 kv = *(const float4*)(kg + goff);
            *(uint2*)(smem + SM_K + off) =
                make_uint2(h2u(__floats2half2_rn(kv.x, kv.y)), h2u(__floats2half2_rn(kv.z, kv.w)));
            float4 vv = *(const float4*)(vg + goff);
            *(uint2*)(smem + SM_V + off) =
                make_uint2(h2u(__floats2half2_rn(vv.x, vv.y)), h2u(__floats2half2_rn(vv.z, vv.w)));
        }
    }
    __syncthreads();

    // ---- QK^T: warp tile 32 rows x 64 cols, fp16 k16 mma ----
    {
        const int i0 = (warp >> 1) * 32;
        const int j0 = (warp & 1) * 64;
        uint32_t A[2][2][4];
        #pragma unroll
        for (int mt = 0; mt < 2; mt++)
            #pragma unroll
            for (int ks = 0; ks < 2; ks++) {
                int row = i0 + mt*16 + (lane & 15);
                int c   = 2*ks + (lane >> 4);
                ldm_x4(A[mt][ks][0], A[mt][ks][1], A[mt][ks][2], A[mt][ks][3],
                       sbase + SM_Q + swz64(row, c));
            }
        float acc[2][8][4];
        #pragma unroll
        for (int mt = 0; mt < 2; mt++)
            #pragma unroll
            for (int nt = 0; nt < 8; nt++)
                #pragma unroll
                for (int k = 0; k < 4; k++) acc[mt][nt][k] = 0.f;

        #pragma unroll
        for (int ntp = 0; ntp < 4; ntp++) {
            #pragma unroll
            for (int ks = 0; ks < 2; ks++) {
                uint32_t Bv[4];
                int rowj = j0 + ntp*16 + (lane & 7) + ((lane >> 4) << 3);
                int c    = 2*ks + ((lane >> 3) & 1);
                ldm_x4(Bv[0], Bv[1], Bv[2], Bv[3], sbase + SM_K + swz64(rowj, c));
                #pragma unroll
                for (int mt = 0; mt < 2; mt++) {
                    mma_f16(acc[mt][2*ntp],     A[mt][ks], Bv[0], Bv[1]);
                    mma_f16(acc[mt][2*ntp + 1], A[mt][ks], Bv[2], Bv[3]);
                }
            }
        }
        // epilogue: add bias (half), write S fp32
        const __half* bias_p = g_biash + (((size_t)win*NHEADS + h) << 14);
        #pragma unroll
        for (int mt = 0; mt < 2; mt++) {
            #pragma unroll
            for (int nt = 0; nt < 8; nt++) {
                int i = i0 + mt*16 + g;
                int j = j0 + nt*8 + 2*tig;
                float2 bv = __half22float2(*(const __half2*)(bias_p + i*NTOK + j));
                *(float2*)(S + i*SP + j) = make_float2(acc[mt][nt][0] + bv.x, acc[mt][nt][1] + bv.y);
                i += 8;
                bv = __half22float2(*(const __half2*)(bias_p + i*NTOK + j));
                *(float2*)(S + i*SP + j) = make_float2(acc[mt][nt][2] + bv.x, acc[mt][nt][3] + bv.y);
            }
        }
    }
    __syncthreads();

    // ---- softmax (base-2) rows warp*16..+16; write P (half) into SM_P ----
    {
        for (int rr = 0; rr < 16; rr++) {
            int r = warp*16 + rr;
            float4 s4 = *(const float4*)(S + r*SP + 4*lane);
            float m = fmaxf(fmaxf(s4.x, s4.y), fmaxf(s4.z, s4.w));
            #pragma unroll
            for (int off = 16; off; off >>= 1)
                m = fmaxf(m, __shfl_xor_sync(0xffffffffu, m, off));
            float e0 = ex2f(s4.x - m), e1 = ex2f(s4.y - m);
            float e2 = ex2f(s4.z - m), e3 = ex2f(s4.w - m);
            float ps = (e0 + e1) + (e2 + e3);
            #pragma unroll
            for (int off = 16; off; off >>= 1)
                ps += __shfl_xor_sync(0xffffffffu, ps, off);
            float inv = __fdividef(1.f, ps);
            uint2 pv = make_uint2(h2u(__floats2half2_rn(e0*inv, e1*inv)),
                                  h2u(__floats2half2_rn(e2*inv, e3*inv)));
            // 4 halves at (row r, half-col 4*lane): chunk = lane>>1, 8B half = lane&1
            uint32_t off8 = swz256(r, lane >> 1) + ((lane & 1) << 3);
            *(uint2*)(smem + SM_P + off8) = pv;
        }
    }
    __syncthreads();

    // ---- P @ V: warp rows warp*16..+16, cols 0..31 ----
    {
        const int i0 = warp * 16;
        float acc[4][4];
        #pragma unroll
        for (int nt = 0; nt < 4; nt++)
            #pragma unroll
            for (int k = 0; k < 4; k++) acc[nt][k] = 0.f;

        #pragma unroll 2
        for (int ks = 0; ks < 8; ks++) {
            uint32_t A[4];
            {
                int row = i0 + (lane & 15);
                int c   = 2*ks + (lane >> 4);
                ldm_x4(A[0], A[1], A[2], A[3], sbase + SM_P + swz256(row, c));
            }
            #pragma unroll
            for (int ntp = 0; ntp < 2; ntp++) {
                uint32_t Bv[4];
                int rowk = ks*16 + (lane & 7) + (((lane >> 3) & 1) << 3);
                int c    = 2*ntp + (lane >> 4);
                ldm_x4_t(Bv[0], Bv[1], Bv[2], Bv[3], sbase + SM_V + swz64(rowk, c));
                mma_f16(acc[2*ntp],     A, Bv[0], Bv[1]);
                mma_f16(acc[2*ntp + 1], A, Bv[2], Bv[3]);
            }
        }
        #pragma unroll
        for (int nt = 0; nt < 4; nt++) {
            int d = nt*8 + 2*tig;
            int i = i0 + g;
            int y = hb*8 + (i >> 4);
            int x = wb*16 + (i & 15);
            float* op = outg + ((size_t)((b*Hdim + y)*Wdim + x))*C_ + h*HD + d;
            *(float2*)op = make_float2(acc[nt][0], acc[nt][1]);
            i += 8;
            y = hb*8 + (i >> 4);
            x = wb*16 + (i & 15);
            op = outg + ((size_t)((b*Hdim + y)*Wdim + x))*C_ + h*HD + d;
            *(float2*)op = make_float2(acc[nt][2], acc[nt][3]);
        }
    }
}

// ---------------------------------------------------------------------------
extern "C" void kernel_launch(void* const* d_in, const int* in_sizes, int n_in,
                              void* d_out, int out_size)
{
    const float* qkv  = (const float*)d_in[0];
    const float* mask = (const float*)d_in[1];
    const float* w0   = (const float*)d_in[2];
    const float* b0   = (const float*)d_in[3];
    const float* g1   = (const float*)d_in[4];
    const float* be1  = (const float*)d_in[5];
    const float* w1   = (const float*)d_in[6];
    const float* lb1  = (const float*)d_in[7];
    const float* g2   = (const float*)d_in[8];
    const float* be2  = (const float*)d_in[9];
    const float* w2   = (const float*)d_in[10];
    const float* lb2  = (const float*)d_in[11];
    const float* g3   = (const float*)d_in[12];
    const float* be3  = (const float*)d_in[13];
    const float* w3   = (const float*)d_in[14];
    const float* lb3  = (const float*)d_in[15];
    const float* rpe  = (const float*)d_in[16];
    const int*   rel  = (const int*)d_in[17];

    const float* q_g = qkv;
    const float* k_g = qkv + (size_t)B_ * L_ * C_;
    const float* v_g = qkv + 2 * (size_t)B_ * L_ * C_;
    float* out = (float*)d_out;

    pos_mlp_kernel<<<4, 128>>>(rpe, w0, b0, g1, be1, w1, lb1,
                               g2, be2, w2, lb2, g3, be3, w3, lb3);
    bias_kernel<<<dim3(16, NHEADS, NWIN), 256>>>(mask, rel);
    pool_kernel<<<dim3(NTOK, B_), C_>>>(q_g);

    cudaFuncSetAttribute(attn_kernel, cudaFuncAttributeMaxDynamicSharedMemorySize, SM_TOT);
    attn_kernel<<<dim3(NHEADS, B_*NWIN), 256, SM_TOT>>>(k_g, v_g, out);
}

// round 6
// speedup vs baseline: 2.8188x; 1.7575x over previous
#include <cuda_runtime.h>
#include <cuda_fp16.h>
#include <cstdint>

#define B_      8
#define Hdim    128
#define Wdim    128
#define C_      192
#define L_      (Hdim*Wdim)
#define NHEADS  6
#define HD      32
#define NTOK    128
#define NWIN    128
#define POSDIM  12
#define NBIAS   465
#define SCALE   0.17677669529663687f
#define LOG2E   1.4426950408889634f

// Scratch (device globals)
__device__ __half g_qph[B_*NHEADS*NTOK*HD];               // pooled queries, *SCALE*LOG2E
__device__ float  g_pos[NBIAS*NHEADS];
__device__ __half g_biash[(size_t)NWIN*NHEADS*NTOK*NTOK]; // (rpb+mask)*LOG2E

__device__ __forceinline__ float ex2f(float x) {
    asm("ex2.approx.ftz.f32 %0, %1;" : "=f"(x) : "f"(x));
    return x;
}
__device__ __forceinline__ uint32_t smem_u32(const void* p) {
    uint32_t a;
    asm("{ .reg .u64 t; cvta.to.shared.u64 t, %1; cvt.u32.u64 %0, t; }" : "=r"(a) : "l"(p));
    return a;
}
__device__ __forceinline__ void ldm_x4(uint32_t& r0, uint32_t& r1, uint32_t& r2, uint32_t& r3, uint32_t addr) {
    asm volatile("ldmatrix.sync.aligned.m8n8.x4.shared.b16 {%0,%1,%2,%3}, [%4];"
                 : "=r"(r0), "=r"(r1), "=r"(r2), "=r"(r3) : "r"(addr));
}
__device__ __forceinline__ void ldm_x4_t(uint32_t& r0, uint32_t& r1, uint32_t& r2, uint32_t& r3, uint32_t addr) {
    asm volatile("ldmatrix.sync.aligned.m8n8.x4.trans.shared.b16 {%0,%1,%2,%3}, [%4];"
                 : "=r"(r0), "=r"(r1), "=r"(r2), "=r"(r3) : "r"(addr));
}
__device__ __forceinline__ void mma_f16(float* c, const uint32_t* a, uint32_t b0, uint32_t b1) {
    asm volatile(
        "mma.sync.aligned.m16n8k16.row.col.f32.f16.f16.f32 "
        "{%0,%1,%2,%3}, {%4,%5,%6,%7}, {%8,%9}, {%0,%1,%2,%3};"
        : "+f"(c[0]), "+f"(c[1]), "+f"(c[2]), "+f"(c[3])
        : "r"(a[0]), "r"(a[1]), "r"(a[2]), "r"(a[3]), "r"(b0), "r"(b1));
}
__device__ __forceinline__ uint32_t h2u(__half2 h) {
    return *reinterpret_cast<uint32_t*>(&h);
}
__device__ __forceinline__ uint32_t packh2(float a, float b) {
    return h2u(__floats2half2_rn(a, b));
}

// 64B-row swizzle (Q,K,V tiles: 128 rows x 32 half): chunk c in [0,4)
__device__ __forceinline__ uint32_t swz64(int row, int c) {
    return row*64 + ((c ^ ((row >> 1) & 3)) << 4);
}

// smem byte offsets (attn kernel): Q/K/V tiles only, 24KB total
#define SM_Q    0
#define SM_K    8192
#define SM_V    16384
#define SM_TOT  24576

// ---------------------------------------------------------------------------
// Kernel 1: DynamicPosBias MLP
// ---------------------------------------------------------------------------
__global__ void pos_mlp_kernel(
    const float* __restrict__ rpe,
    const float* __restrict__ w0, const float* __restrict__ b0,
    const float* __restrict__ g1, const float* __restrict__ be1,
    const float* __restrict__ w1, const float* __restrict__ lb1,
    const float* __restrict__ g2, const float* __restrict__ be2,
    const float* __restrict__ w2, const float* __restrict__ lb2,
    const float* __restrict__ g3, const float* __restrict__ be3,
    const float* __restrict__ w3, const float* __restrict__ lb3)
{
    int t = blockIdx.x * blockDim.x + threadIdx.x;
    if (t >= NBIAS) return;
    float x[POSDIM], y[POSDIM];
    float a = rpe[2*t], b = rpe[2*t+1];
    #pragma unroll
    for (int o = 0; o < POSDIM; o++)
        x[o] = a * w0[o] + b * w0[POSDIM + o] + b0[o];

    #pragma unroll
    for (int stage = 0; stage < 3; stage++) {
        const float* g  = stage == 0 ? g1  : (stage == 1 ? g2  : g3);
        const float* be = stage == 0 ? be1 : (stage == 1 ? be2 : be3);
        float m = 0.f;
        #pragma unroll
        for (int i = 0; i < POSDIM; i++) m += x[i];
        m *= (1.f/POSDIM);
        float v = 0.f;
        #pragma unroll
        for (int i = 0; i < POSDIM; i++) { float d = x[i]-m; v += d*d; }
        v *= (1.f/POSDIM);
        float inv = rsqrtf(v + 1e-5f);
        #pragma unroll
        for (int i = 0; i < POSDIM; i++)
            y[i] = fmaxf((x[i]-m)*inv*g[i] + be[i], 0.f);
        if (stage < 2) {
            const float* w  = stage == 0 ? w1  : w2;
            const float* lb = stage == 0 ? lb1 : lb2;
            #pragma unroll
            for (int o = 0; o < POSDIM; o++) {
                float s = lb[o];
                #pragma unroll
                for (int i = 0; i < POSDIM; i++) s += y[i] * w[i*POSDIM + o];
                x[o] = s;
            }
        } else {
            #pragma unroll
            for (int o = 0; o < NHEADS; o++) {
                float s = lb3[o];
                #pragma unroll
                for (int i = 0; i < POSDIM; i++) s += y[i] * w3[i*NHEADS + o];
                g_pos[t*NHEADS + o] = s;
            }
        }
    }
}

// ---------------------------------------------------------------------------
// Kernel 2: combined bias (half) = (pos[rel_idx] + mask) * LOG2E
// ---------------------------------------------------------------------------
__global__ void bias_kernel(const float* __restrict__ mask,
                            const int* __restrict__ rel_idx)
{
    int q = blockIdx.x * 256 + threadIdx.x;
    int h   = blockIdx.y;
    int win = blockIdx.z;
    int4  r = ((const int4*)rel_idx)[q];
    float4 m = ((const float4*)(mask + ((size_t)win<<14)))[q];
    uint2 out = make_uint2(
        packh2((g_pos[r.x*NHEADS + h] + m.x) * LOG2E, (g_pos[r.y*NHEADS + h] + m.y) * LOG2E),
        packh2((g_pos[r.z*NHEADS + h] + m.z) * LOG2E, (g_pos[r.w*NHEADS + h] + m.w) * LOG2E));
    ((uint2*)(g_biash + (((size_t)win*NHEADS + h)<<14)))[q] = out;
}

// ---------------------------------------------------------------------------
// Kernel 3: pooled query -> half, scaled by SCALE*LOG2E
// ---------------------------------------------------------------------------
__global__ void pool_kernel(const float* __restrict__ q)
{
    int c = threadIdx.x;
    int n = blockIdx.x;
    int b = blockIdx.y;
    int i = n >> 4;
    int j = n & 15;
    const float* base = q + ((size_t)b * L_) * C_ + c;
    bool is_avg = (c < 96);
    float acc = is_avg ? 0.f : -3.0e38f;
    #pragma unroll 4
    for (int yy = 0; yy < 16; yy++) {
        int y = i*16 + yy;
        const float* row = base + (size_t)(y*Wdim + j*8) * C_;
        #pragma unroll
        for (int xx = 0; xx < 8; xx++) {
            float v = row[(size_t)xx * C_];
            if (is_avg) acc += v; else acc = fmaxf(acc, v);
        }
    }
    if (is_avg) acc *= (1.f/128.f);
    int h = c >> 5, d = c & 31;
    g_qph[(((b*NHEADS) + h)*NTOK + n)*HD + d] = __float2half_rn(acc * (SCALE * LOG2E));
}

// ---------------------------------------------------------------------------
// Kernel 4: fused attention, all-register S/P. One barrier.
// grid=(6,1024), block=256 (8 warps), 24KB smem, 2 blocks/SM.
// ---------------------------------------------------------------------------
__global__ void __launch_bounds__(256, 2)
attn_kernel(const float* __restrict__ kg, const float* __restrict__ vg,
            float* __restrict__ outg)
{
    extern __shared__ char smem[];
    const uint32_t sbase = smem_u32(smem);

    const int t    = threadIdx.x;
    const int warp = t >> 5;
    const int lane = t & 31;
    const int g    = lane >> 2;
    const int tig  = lane & 3;
    const int h    = blockIdx.x;
    const int w    = blockIdx.y;
    const int b    = w >> 7;
    const int win  = w & 127;
    const int hb   = win >> 3;
    const int wb   = win & 7;
    const int qb   = w & 7;

    // ---- load Q (half) + K/V (fp32 -> half) into swizzled smem ----
    {
        const __half* qsrc = g_qph + (((size_t)qb*NHEADS + h)*NTOK)*HD;
        #pragma unroll
        for (int rep = 0; rep < 4; rep++) {
            int idx = t + rep*256;              // 8B chunk id
            int row = idx >> 3, q4 = idx & 7;
            uint32_t off = swz64(row, q4 >> 1) + ((q4 & 1) << 3);
            *(uint2*)(smem + SM_Q + off) = *(const uint2*)(qsrc + idx*4);
        }
        #pragma unroll
        for (int rep = 0; rep < 4; rep++) {
            int idx = t + rep*256;
            int row = idx >> 3, q4 = idx & 7;
            int y = hb*8 + (row >> 4);
            int x = wb*16 + (row & 15);
            size_t goff = ((size_t)(b*L_ + y*Wdim + x))*C_ + h*HD + q4*4;
            uint32_t off = swz64(row, q4 >> 1) + ((q4 & 1) << 3);
            float4 kv = *(const float4*)(kg + goff);
            *(uint2*)(smem + SM_K + off) =
                make_uint2(packh2(kv.x, kv.y), packh2(kv.z, kv.w));
            float4 vv = *(const float4*)(vg + goff);
            *(uint2*)(smem + SM_V + off) =
                make_uint2(packh2(vv.x, vv.y), packh2(vv.z, vv.w));
        }
    }
    __syncthreads();   // the only barrier

    const int i0 = warp * 16;      // this warp owns rows [i0, i0+16)

    // ---- QK^T: warp tile 16 rows x 128 cols ----
    float acc[16][4];
    {
        uint32_t A[2][4];
        #pragma unroll
        for (int ks = 0; ks < 2; ks++) {
            int row = i0 + (lane & 15);
            int c   = 2*ks + (lane >> 4);
            ldm_x4(A[ks][0], A[ks][1], A[ks][2], A[ks][3], sbase + SM_Q + swz64(row, c));
        }
        #pragma unroll
        for (int nt = 0; nt < 16; nt++)
            #pragma unroll
            for (int k = 0; k < 4; k++) acc[nt][k] = 0.f;

        #pragma unroll
        for (int ntp = 0; ntp < 8; ntp++) {
            #pragma unroll
            for (int ks = 0; ks < 2; ks++) {
                uint32_t Bv[4];
                int rowj = ntp*16 + (lane & 7) + ((lane >> 4) << 3);
                int c    = 2*ks + ((lane >> 3) & 1);
                ldm_x4(Bv[0], Bv[1], Bv[2], Bv[3], sbase + SM_K + swz64(rowj, c));
                mma_f16(acc[2*ntp],     A[ks], Bv[0], Bv[1]);
                mma_f16(acc[2*ntp + 1], A[ks], Bv[2], Bv[3]);
            }
        }
    }

    // ---- add bias, register softmax (rows g and g+8), pack P to half ----
    uint32_t ph[8][4];
    float inv0, inv1;
    {
        const __half* bias_p = g_biash + (((size_t)win*NHEADS + h) << 14);
        const __half* bp0 = bias_p + (i0 + g)*NTOK + 2*tig;
        const __half* bp1 = bias_p + (i0 + g + 8)*NTOK + 2*tig;
        float m0 = -3.0e38f, m1 = -3.0e38f;
        #pragma unroll
        for (int nt = 0; nt < 16; nt++) {
            float2 bv0 = __half22float2(*(const __half2*)(bp0 + nt*8));
            float2 bv1 = __half22float2(*(const __half2*)(bp1 + nt*8));
            acc[nt][0] += bv0.x; acc[nt][1] += bv0.y;
            acc[nt][2] += bv1.x; acc[nt][3] += bv1.y;
            m0 = fmaxf(m0, fmaxf(acc[nt][0], acc[nt][1]));
            m1 = fmaxf(m1, fmaxf(acc[nt][2], acc[nt][3]));
        }
        // quad reduce (cols spread over tig = lane&3)
        m0 = fmaxf(m0, __shfl_xor_sync(0xffffffffu, m0, 1));
        m0 = fmaxf(m0, __shfl_xor_sync(0xffffffffu, m0, 2));
        m1 = fmaxf(m1, __shfl_xor_sync(0xffffffffu, m1, 1));
        m1 = fmaxf(m1, __shfl_xor_sync(0xffffffffu, m1, 2));

        float s0 = 0.f, s1 = 0.f;
        #pragma unroll
        for (int nt = 0; nt < 16; nt++) {
            float e0 = ex2f(acc[nt][0] - m0);
            float e1 = ex2f(acc[nt][1] - m0);
            float e2 = ex2f(acc[nt][2] - m1);
            float e3 = ex2f(acc[nt][3] - m1);
            s0 += e0 + e1;
            s1 += e2 + e3;
            // pack into PV A-fragments: ks = nt>>1
            if ((nt & 1) == 0) {
                ph[nt >> 1][0] = packh2(e0, e1);
                ph[nt >> 1][1] = packh2(e2, e3);
            } else {
                ph[nt >> 1][2] = packh2(e0, e1);
                ph[nt >> 1][3] = packh2(e2, e3);
            }
        }
        s0 += __shfl_xor_sync(0xffffffffu, s0, 1);
        s0 += __shfl_xor_sync(0xffffffffu, s0, 2);
        s1 += __shfl_xor_sync(0xffffffffu, s1, 1);
        s1 += __shfl_xor_sync(0xffffffffu, s1, 2);
        inv0 = __fdividef(1.f, s0);
        inv1 = __fdividef(1.f, s1);
    }

    // ---- P @ V: rows [i0, i0+16), cols 0..31; P unnormalized in regs ----
    {
        float o[4][4];
        #pragma unroll
        for (int nt = 0; nt < 4; nt++)
            #pragma unroll
            for (int k = 0; k < 4; k++) o[nt][k] = 0.f;

        #pragma unroll
        for (int ks = 0; ks < 8; ks++) {
            #pragma unroll
            for (int ntp = 0; ntp < 2; ntp++) {
                uint32_t Bv[4];
                int rowk = ks*16 + (lane & 7) + (((lane >> 3) & 1) << 3);
                int c    = 2*ntp + (lane >> 4);
                ldm_x4_t(Bv[0], Bv[1], Bv[2], Bv[3], sbase + SM_V + swz64(rowk, c));
                mma_f16(o[2*ntp],     ph[ks], Bv[0], Bv[1]);
                mma_f16(o[2*ntp + 1], ph[ks], Bv[2], Bv[3]);
            }
        }
        #pragma unroll
        for (int nt = 0; nt < 4; nt++) {
            int d = nt*8 + 2*tig;
            int i = i0 + g;
            int y = hb*8 + (i >> 4);
            int x = wb*16 + (i & 15);
            float* op = outg + ((size_t)((b*Hdim + y)*Wdim + x))*C_ + h*HD + d;
            *(float2*)op = make_float2(o[nt][0]*inv0, o[nt][1]*inv0);
            i += 8;
            y = hb*8 + (i >> 4);
            x = wb*16 + (i & 15);
            op = outg + ((size_t)((b*Hdim + y)*Wdim + x))*C_ + h*HD + d;
            *(float2*)op = make_float2(o[nt][2]*inv1, o[nt][3]*inv1);
        }
    }
}

// ---------------------------------------------------------------------------
extern "C" void kernel_launch(void* const* d_in, const int* in_sizes, int n_in,
                              void* d_out, int out_size)
{
    const float* qkv  = (const float*)d_in[0];
    const float* mask = (const float*)d_in[1];
    const float* w0   = (const float*)d_in[2];
    const float* b0   = (const float*)d_in[3];
    const float* g1   = (const float*)d_in[4];
    const float* be1  = (const float*)d_in[5];
    const float* w1   = (const float*)d_in[6];
    const float* lb1  = (const float*)d_in[7];
    const float* g2   = (const float*)d_in[8];
    const float* be2  = (const float*)d_in[9];
    const float* w2   = (const float*)d_in[10];
    const float* lb2  = (const float*)d_in[11];
    const float* g3   = (const float*)d_in[12];
    const float* be3  = (const float*)d_in[13];
    const float* w3   = (const float*)d_in[14];
    const float* lb3  = (const float*)d_in[15];
    const float* rpe  = (const float*)d_in[16];
    const int*   rel  = (const int*)d_in[17];

    const float* q_g = qkv;
    const float* k_g = qkv + (size_t)B_ * L_ * C_;
    const float* v_g = qkv + 2 * (size_t)B_ * L_ * C_;
    float* out = (float*)d_out;

    pos_mlp_kernel<<<4, 128>>>(rpe, w0, b0, g1, be1, w1, lb1,
                               g2, be2, w2, lb2, g3, be3, w3, lb3);
    bias_kernel<<<dim3(16, NHEADS, NWIN), 256>>>(mask, rel);
    pool_kernel<<<dim3(NTOK, B_), C_>>>(q_g);

    cudaFuncSetAttribute(attn_kernel, cudaFuncAttributeMaxDynamicSharedMemorySize, SM_TOT);
    attn_kernel<<<dim3(NHEADS, B_*NWIN), 256, SM_TOT>>>(k_g, v_g, out);
}

// round 7
// speedup vs baseline: 3.4485x; 1.2234x over previous
#include <cuda_runtime.h>
#include <cuda_fp16.h>
#include <cstdint>

#define B_      8
#define Hdim    128
#define Wdim    128
#define C_      192
#define L_      (Hdim*Wdim)
#define NHEADS  6
#define HD      32
#define NTOK    128
#define NWIN    128
#define POSDIM  12
#define NBIAS   465
#define SCALE   0.17677669529663687f
#define LOG2E   1.4426950408889634f

// Scratch (device globals)
__device__ __half g_qph[B_*NHEADS*NTOK*HD];               // pooled queries, *SCALE*LOG2E
__device__ float  g_pos[NBIAS*NHEADS];
// fragment-permuted bias: uint4 index = (((win*6+h)*8 + warpB)*8 + m)*32 + lane
// each uint4 = 8 halves: [nt=2m+ (e>>2)]: e&3 = r*2+p  (r: row g / g+8, p: col parity)
__device__ __half g_biasf[(size_t)NWIN*NHEADS*NTOK*NTOK];

__device__ __forceinline__ float ex2f(float x) {
    asm("ex2.approx.ftz.f32 %0, %1;" : "=f"(x) : "f"(x));
    return x;
}
__device__ __forceinline__ uint32_t smem_u32(const void* p) {
    uint32_t a;
    asm("{ .reg .u64 t; cvta.to.shared.u64 t, %1; cvt.u32.u64 %0, t; }" : "=r"(a) : "l"(p));
    return a;
}
__device__ __forceinline__ void ldm_x4(uint32_t& r0, uint32_t& r1, uint32_t& r2, uint32_t& r3, uint32_t addr) {
    asm volatile("ldmatrix.sync.aligned.m8n8.x4.shared.b16 {%0,%1,%2,%3}, [%4];"
                 : "=r"(r0), "=r"(r1), "=r"(r2), "=r"(r3) : "r"(addr));
}
__device__ __forceinline__ void ldm_x4_t(uint32_t& r0, uint32_t& r1, uint32_t& r2, uint32_t& r3, uint32_t addr) {
    asm volatile("ldmatrix.sync.aligned.m8n8.x4.trans.shared.b16 {%0,%1,%2,%3}, [%4];"
                 : "=r"(r0), "=r"(r1), "=r"(r2), "=r"(r3) : "r"(addr));
}
__device__ __forceinline__ void mma_f16(float* c, const uint32_t* a, uint32_t b0, uint32_t b1) {
    asm volatile(
        "mma.sync.aligned.m16n8k16.row.col.f32.f16.f16.f32 "
        "{%0,%1,%2,%3}, {%4,%5,%6,%7}, {%8,%9}, {%0,%1,%2,%3};"
        : "+f"(c[0]), "+f"(c[1]), "+f"(c[2]), "+f"(c[3])
        : "r"(a[0]), "r"(a[1]), "r"(a[2]), "r"(a[3]), "r"(b0), "r"(b1));
}
__device__ __forceinline__ uint32_t h2u(__half2 h) {
    return *reinterpret_cast<uint32_t*>(&h);
}
__device__ __forceinline__ uint32_t packh2(float a, float b) {
    return h2u(__floats2half2_rn(a, b));
}

// 64B-row swizzle (Q,K,V tiles: 128 rows x 32 half): chunk c in [0,4)
__device__ __forceinline__ uint32_t swz64(int row, int c) {
    return row*64 + ((c ^ ((row >> 1) & 3)) << 4);
}

// smem byte offsets (attn kernel): Q/K/V tiles only, 24KB total
#define SM_Q    0
#define SM_K    8192
#define SM_V    16384
#define SM_TOT  24576

// ---------------------------------------------------------------------------
// Kernel 1: DynamicPosBias MLP
// ---------------------------------------------------------------------------
__global__ void pos_mlp_kernel(
    const float* __restrict__ rpe,
    const float* __restrict__ w0, const float* __restrict__ b0,
    const float* __restrict__ g1, const float* __restrict__ be1,
    const float* __restrict__ w1, const float* __restrict__ lb1,
    const float* __restrict__ g2, const float* __restrict__ be2,
    const float* __restrict__ w2, const float* __restrict__ lb2,
    const float* __restrict__ g3, const float* __restrict__ be3,
    const float* __restrict__ w3, const float* __restrict__ lb3)
{
    int t = blockIdx.x * blockDim.x + threadIdx.x;
    if (t >= NBIAS) return;
    float x[POSDIM], y[POSDIM];
    float a = rpe[2*t], b = rpe[2*t+1];
    #pragma unroll
    for (int o = 0; o < POSDIM; o++)
        x[o] = a * w0[o] + b * w0[POSDIM + o] + b0[o];

    #pragma unroll
    for (int stage = 0; stage < 3; stage++) {
        const float* g  = stage == 0 ? g1  : (stage == 1 ? g2  : g3);
        const float* be = stage == 0 ? be1 : (stage == 1 ? be2 : be3);
        float m = 0.f;
        #pragma unroll
        for (int i = 0; i < POSDIM; i++) m += x[i];
        m *= (1.f/POSDIM);
        float v = 0.f;
        #pragma unroll
        for (int i = 0; i < POSDIM; i++) { float d = x[i]-m; v += d*d; }
        v *= (1.f/POSDIM);
        float inv = rsqrtf(v + 1e-5f);
        #pragma unroll
        for (int i = 0; i < POSDIM; i++)
            y[i] = fmaxf((x[i]-m)*inv*g[i] + be[i], 0.f);
        if (stage < 2) {
            const float* w  = stage == 0 ? w1  : w2;
            const float* lb = stage == 0 ? lb1 : lb2;
            #pragma unroll
            for (int o = 0; o < POSDIM; o++) {
                float s = lb[o];
                #pragma unroll
                for (int i = 0; i < POSDIM; i++) s += y[i] * w[i*POSDIM + o];
                x[o] = s;
            }
        } else {
            #pragma unroll
            for (int o = 0; o < NHEADS; o++) {
                float s = lb3[o];
                #pragma unroll
                for (int i = 0; i < POSDIM; i++) s += y[i] * w3[i*NHEADS + o];
                g_pos[t*NHEADS + o] = s;
            }
        }
    }
}

// ---------------------------------------------------------------------------
// Kernel 2 (fused prep): blocks [0,768): bias permuted table; [768,1792): pool.
// ---------------------------------------------------------------------------
__global__ void prep_kernel(const float* __restrict__ mask,
                            const int* __restrict__ rel_idx,
                            const float* __restrict__ q)
{
    int bx = blockIdx.x;
    int t  = threadIdx.x;
    if (bx < 768) {
        // ---- bias: one block per (win, h); thread = (warpB, lane), loops m ----
        int win = bx / 6;
        int h   = bx - win*6;
        int warpB = t >> 5;
        int lane  = t & 31;
        int g   = lane >> 2;
        int tig = lane & 3;
        const float* maskp = mask + ((size_t)win << 14);
        uint4* outp = (uint4*)g_biasf + ((((size_t)win*NHEADS + h)*8 + warpB)*8)*32 + lane;
        int i0 = warpB*16 + g;
        #pragma unroll
        for (int m = 0; m < 8; m++) {
            uint4 o;
            uint32_t wv[4];
            #pragma unroll
            for (int sub = 0; sub < 2; sub++) {
                int j0 = (2*m + sub)*8 + tig*2;
                #pragma unroll
                for (int r = 0; r < 2; r++) {
                    int i = i0 + r*8;
                    int2   rr = *(const int2*)(rel_idx + i*NTOK + j0);
                    float2 mm = *(const float2*)(maskp + i*NTOK + j0);
                    wv[sub*2 + r] = packh2((g_pos[rr.x*NHEADS + h] + mm.x) * LOG2E,
                                           (g_pos[rr.y*NHEADS + h] + mm.y) * LOG2E);
                }
            }
            o.x = wv[0]; o.y = wv[1]; o.z = wv[2]; o.w = wv[3];
            outp[m*32] = o;
        }
    } else {
        // ---- pool: one block per (token n, batch b) ----
        int bi = bx - 768;
        int b = bi >> 7;
        int n = bi & 127;
        int c = t;
        if (c >= C_) return;
        int i = n >> 4;
        int j = n & 15;
        const float* base = q + ((size_t)b * L_) * C_ + c;
        bool is_avg = (c < 96);
        float acc = is_avg ? 0.f : -3.0e38f;
        #pragma unroll 4
        for (int yy = 0; yy < 16; yy++) {
            int y = i*16 + yy;
            const float* row = base + (size_t)(y*Wdim + j*8) * C_;
            #pragma unroll
            for (int xx = 0; xx < 8; xx++) {
                float v = row[(size_t)xx * C_];
                if (is_avg) acc += v; else acc = fmaxf(acc, v);
            }
        }
        if (is_avg) acc *= (1.f/128.f);
        int h = c >> 5, d = c & 31;
        g_qph[(((b*NHEADS) + h)*NTOK + n)*HD + d] = __float2half_rn(acc * (SCALE * LOG2E));
    }
}

// ---------------------------------------------------------------------------
// Kernel 3: fused attention, all-register S/P, permuted bias.
// grid=(6,1024), block=256 (8 warps), 24KB smem, 2 blocks/SM.
// ---------------------------------------------------------------------------
__global__ void __launch_bounds__(256, 2)
attn_kernel(const float* __restrict__ kg, const float* __restrict__ vg,
            float* __restrict__ outg)
{
    extern __shared__ char smem[];
    const uint32_t sbase = smem_u32(smem);

    const int t    = threadIdx.x;
    const int warp = t >> 5;
    const int lane = t & 31;
    const int g    = lane >> 2;
    const int tig  = lane & 3;
    const int h    = blockIdx.x;
    const int w    = blockIdx.y;
    const int b    = w >> 7;
    const int win  = w & 127;
    const int hb   = win >> 3;
    const int wb   = win & 7;
    const int qb   = w & 7;

    // ---- load Q (half) + K/V (fp32 -> half) into swizzled smem ----
    {
        const __half* qsrc = g_qph + (((size_t)qb*NHEADS + h)*NTOK)*HD;
        #pragma unroll
        for (int rep = 0; rep < 4; rep++) {
            int idx = t + rep*256;              // 8B chunk id
            int row = idx >> 3, q4 = idx & 7;
            uint32_t off = swz64(row, q4 >> 1) + ((q4 & 1) << 3);
            *(uint2*)(smem + SM_Q + off) = *(const uint2*)(qsrc + idx*4);
        }
        #pragma unroll
        for (int rep = 0; rep < 4; rep++) {
            int idx = t + rep*256;
            int row = idx >> 3, q4 = idx & 7;
            int y = hb*8 + (row >> 4);
            int x = wb*16 + (row & 15);
            size_t goff = ((size_t)(b*L_ + y*Wdim + x))*C_ + h*HD + q4*4;
            uint32_t off = swz64(row, q4 >> 1) + ((q4 & 1) << 3);
            float4 kv = *(const float4*)(kg + goff);
            *(uint2*)(smem + SM_K + off) =
                make_uint2(packh2(kv.x, kv.y), packh2(kv.z, kv.w));
            float4 vv = *(const float4*)(vg + goff);
            *(uint2*)(smem + SM_V + off) =
                make_uint2(packh2(vv.x, vv.y), packh2(vv.z, vv.w));
        }
    }
    __syncthreads();   // the only barrier

    const int i0 = warp * 16;      // this warp owns rows [i0, i0+16)

    // ---- prefetch permuted bias: 8 x LDG.128 per thread, coalesced ----
    uint4 Bb[8];
    {
        const uint4* bf = (const uint4*)g_biasf
            + ((((size_t)win*NHEADS + h)*8 + warp)*8)*32 + lane;
        #pragma unroll
        for (int m = 0; m < 8; m++)
            Bb[m] = bf[m*32];
    }

    // ---- QK^T: warp tile 16 rows x 128 cols ----
    float acc[16][4];
    {
        uint32_t A[2][4];
        #pragma unroll
        for (int ks = 0; ks < 2; ks++) {
            int row = i0 + (lane & 15);
            int c   = 2*ks + (lane >> 4);
            ldm_x4(A[ks][0], A[ks][1], A[ks][2], A[ks][3], sbase + SM_Q + swz64(row, c));
        }
        #pragma unroll
        for (int nt = 0; nt < 16; nt++)
            #pragma unroll
            for (int k = 0; k < 4; k++) acc[nt][k] = 0.f;

        #pragma unroll
        for (int ntp = 0; ntp < 8; ntp++) {
            #pragma unroll
            for (int ks = 0; ks < 2; ks++) {
                uint32_t Bv[4];
                int rowj = ntp*16 + (lane & 7) + ((lane >> 4) << 3);
                int c    = 2*ks + ((lane >> 3) & 1);
                ldm_x4(Bv[0], Bv[1], Bv[2], Bv[3], sbase + SM_K + swz64(rowj, c));
                mma_f16(acc[2*ntp],     A[ks], Bv[0], Bv[1]);
                mma_f16(acc[2*ntp + 1], A[ks], Bv[2], Bv[3]);
            }
        }
    }

    // ---- add bias (from fragment-layout regs), register softmax, pack P ----
    uint32_t ph[8][4];
    float inv0, inv1;
    {
        float m0 = -3.0e38f, m1 = -3.0e38f;
        #pragma unroll
        for (int nt = 0; nt < 16; nt++) {
            int m = nt >> 1;
            uint32_t w0 = (nt & 1) ? Bb[m].z : Bb[m].x;
            uint32_t w1 = (nt & 1) ? Bb[m].w : Bb[m].y;
            float2 bv0 = __half22float2(*reinterpret_cast<__half2*>(&w0));
            float2 bv1 = __half22float2(*reinterpret_cast<__half2*>(&w1));
            acc[nt][0] += bv0.x; acc[nt][1] += bv0.y;
            acc[nt][2] += bv1.x; acc[nt][3] += bv1.y;
            m0 = fmaxf(m0, fmaxf(acc[nt][0], acc[nt][1]));
            m1 = fmaxf(m1, fmaxf(acc[nt][2], acc[nt][3]));
        }
        m0 = fmaxf(m0, __shfl_xor_sync(0xffffffffu, m0, 1));
        m0 = fmaxf(m0, __shfl_xor_sync(0xffffffffu, m0, 2));
        m1 = fmaxf(m1, __shfl_xor_sync(0xffffffffu, m1, 1));
        m1 = fmaxf(m1, __shfl_xor_sync(0xffffffffu, m1, 2));

        float s0 = 0.f, s1 = 0.f;
        #pragma unroll
        for (int nt = 0; nt < 16; nt++) {
            float e0 = ex2f(acc[nt][0] - m0);
            float e1 = ex2f(acc[nt][1] - m0);
            float e2 = ex2f(acc[nt][2] - m1);
            float e3 = ex2f(acc[nt][3] - m1);
            s0 += e0 + e1;
            s1 += e2 + e3;
            if ((nt & 1) == 0) {
                ph[nt >> 1][0] = packh2(e0, e1);
                ph[nt >> 1][1] = packh2(e2, e3);
            } else {
                ph[nt >> 1][2] = packh2(e0, e1);
                ph[nt >> 1][3] = packh2(e2, e3);
            }
        }
        s0 += __shfl_xor_sync(0xffffffffu, s0, 1);
        s0 += __shfl_xor_sync(0xffffffffu, s0, 2);
        s1 += __shfl_xor_sync(0xffffffffu, s1, 1);
        s1 += __shfl_xor_sync(0xffffffffu, s1, 2);
        inv0 = __fdividef(1.f, s0);
        inv1 = __fdividef(1.f, s1);
    }

    // ---- P @ V: rows [i0, i0+16), cols 0..31; P unnormalized in regs ----
    {
        float o[4][4];
        #pragma unroll
        for (int nt = 0; nt < 4; nt++)
            #pragma unroll
            for (int k = 0; k < 4; k++) o[nt][k] = 0.f;

        #pragma unroll
        for (int ks = 0; ks < 8; ks++) {
            #pragma unroll
            for (int ntp = 0; ntp < 2; ntp++) {
                uint32_t Bv[4];
                int rowk = ks*16 + (lane & 7) + (((lane >> 3) & 1) << 3);
                int c    = 2*ntp + (lane >> 4);
                ldm_x4_t(Bv[0], Bv[1], Bv[2], Bv[3], sbase + SM_V + swz64(rowk, c));
                mma_f16(o[2*ntp],     ph[ks], Bv[0], Bv[1]);
                mma_f16(o[2*ntp + 1], ph[ks], Bv[2], Bv[3]);
            }
        }
        #pragma unroll
        for (int nt = 0; nt < 4; nt++) {
            int d = nt*8 + 2*tig;
            int i = i0 + g;
            int y = hb*8 + (i >> 4);
            int x = wb*16 + (i & 15);
            float* op = outg + ((size_t)((b*Hdim + y)*Wdim + x))*C_ + h*HD + d;
            *(float2*)op = make_float2(o[nt][0]*inv0, o[nt][1]*inv0);
            i += 8;
            y = hb*8 + (i >> 4);
            x = wb*16 + (i & 15);
            op = outg + ((size_t)((b*Hdim + y)*Wdim + x))*C_ + h*HD + d;
            *(float2*)op = make_float2(o[nt][2]*inv1, o[nt][3]*inv1);
        }
    }
}

// ---------------------------------------------------------------------------
extern "C" void kernel_launch(void* const* d_in, const int* in_sizes, int n_in,
                              void* d_out, int out_size)
{
    const float* qkv  = (const float*)d_in[0];
    const float* mask = (const float*)d_in[1];
    const float* w0   = (const float*)d_in[2];
    const float* b0   = (const float*)d_in[3];
    const float* g1   = (const float*)d_in[4];
    const float* be1  = (const float*)d_in[5];
    const float* w1   = (const float*)d_in[6];
    const float* lb1  = (const float*)d_in[7];
    const float* g2   = (const float*)d_in[8];
    const float* be2  = (const float*)d_in[9];
    const float* w2   = (const float*)d_in[10];
    const float* lb2  = (const float*)d_in[11];
    const float* g3   = (const float*)d_in[12];
    const float* be3  = (const float*)d_in[13];
    const float* w3   = (const float*)d_in[14];
    const float* lb3  = (const float*)d_in[15];
    const float* rpe  = (const float*)d_in[16];
    const int*   rel  = (const int*)d_in[17];

    const float* q_g = qkv;
    const float* k_g = qkv + (size_t)B_ * L_ * C_;
    const float* v_g = qkv + 2 * (size_t)B_ * L_ * C_;
    float* out = (float*)d_out;

    pos_mlp_kernel<<<4, 128>>>(rpe, w0, b0, g1, be1, w1, lb1,
                               g2, be2, w2, lb2, g3, be3, w3, lb3);
    prep_kernel<<<768 + 1024, 256>>>(mask, rel, q_g);

    cudaFuncSetAttribute(attn_kernel, cudaFuncAttributeMaxDynamicSharedMemorySize, SM_TOT);
    attn_kernel<<<dim3(NHEADS, B_*NWIN), 256, SM_TOT>>>(k_g, v_g, out);
}